// round 3
// baseline (speedup 1.0000x reference)
#include <cuda_runtime.h>
#include <cuda_bf16.h>
#include <math.h>

// Problem constants
#define B_  4
#define T_  2048
#define D_  1024
#define H_  16
#define DH_ 64
#define ROWS_ (B_*T_)          // 8192
#define ELEMS_ ((size_t)ROWS_*D_)  // 8,388,608

// Scratch (device globals — no allocation)
__device__ float g_q[ELEMS_];
__device__ float g_k[ELEMS_];
__device__ float g_v[ELEMS_];
__device__ float g_att[ELEMS_];

// ---------------------------------------------------------------------------
// SGEMM: C[M,N] = A[M,K] @ B[K,N], all row-major fp32.
// BM=BN=128, BK=8, 256 threads, 8x8 microtile. Assumes M%128==0, N%128==0, K%8==0.
// ---------------------------------------------------------------------------
__global__ __launch_bounds__(256) void sgemm128(const float* __restrict__ A,
                                                const float* __restrict__ Bm,
                                                float* __restrict__ C,
                                                int M, int N, int K)
{
    const int BM = 128, BN = 128, BK = 8;
    __shared__ float As[BK][BM];
    __shared__ float Bs[BK][BN];

    int tid = threadIdx.x;
    int bx = blockIdx.x, by = blockIdx.y;
    int row0 = by * BM, col0 = bx * BN;

    // A tile load mapping: 128x8 = 256 float4, one per thread
    int a_r = tid >> 1;          // 0..127
    int a_c = (tid & 1) * 4;     // 0 or 4
    // B tile load mapping: 8x128 = 256 float4, one per thread
    int b_r = tid >> 5;          // 0..7
    int b_c = (tid & 31) * 4;

    int tx = tid & 15, ty = tid >> 4;   // 16x16 thread grid

    float acc[8][8];
    #pragma unroll
    for (int i = 0; i < 8; i++)
        #pragma unroll
        for (int j = 0; j < 8; j++) acc[i][j] = 0.f;

    for (int k0 = 0; k0 < K; k0 += BK) {
        float4 av = *(const float4*)&A[(size_t)(row0 + a_r) * K + k0 + a_c];
        As[a_c + 0][a_r] = av.x;
        As[a_c + 1][a_r] = av.y;
        As[a_c + 2][a_r] = av.z;
        As[a_c + 3][a_r] = av.w;
        float4 bv = *(const float4*)&Bm[(size_t)(k0 + b_r) * N + col0 + b_c];
        *(float4*)&Bs[b_r][b_c] = bv;
        __syncthreads();

        #pragma unroll
        for (int k = 0; k < BK; k++) {
            float ra[8], rb[8];
            #pragma unroll
            for (int i = 0; i < 8; i++) ra[i] = As[k][ty * 8 + i];
            #pragma unroll
            for (int j = 0; j < 8; j++) rb[j] = Bs[k][tx * 8 + j];
            #pragma unroll
            for (int i = 0; i < 8; i++)
                #pragma unroll
                for (int j = 0; j < 8; j++)
                    acc[i][j] += ra[i] * rb[j];
        }
        __syncthreads();
    }

    #pragma unroll
    for (int i = 0; i < 8; i++) {
        size_t crow = (size_t)(row0 + ty * 8 + i) * N + col0 + tx * 8;
        float4 v0 = make_float4(acc[i][0], acc[i][1], acc[i][2], acc[i][3]);
        float4 v1 = make_float4(acc[i][4], acc[i][5], acc[i][6], acc[i][7]);
        *(float4*)&C[crow] = v0;
        *(float4*)&C[crow + 4] = v1;
    }
}

// ---------------------------------------------------------------------------
// RoPE: in-place on Q and K. Layout (B*T, H, Dh) contiguous.
// rotate_half: out[i]     = x[i]*c[i]     - x[i+32]*s[i]        (i < 32)
//              out[i+32]  = x[i+32]*c[i+32] + x[i]*s[i+32]
// ---------------------------------------------------------------------------
__global__ __launch_bounds__(256) void rope_kernel(float* __restrict__ Q,
                                                   float* __restrict__ Kv,
                                                   const float* __restrict__ cosp,
                                                   const float* __restrict__ sinp)
{
    int idx = blockIdx.x * blockDim.x + threadIdx.x;   // over ROWS_*H_*32
    if (idx >= ROWS_ * H_ * 32) return;
    int i = idx & 31;
    int row = idx >> 5;                 // (b*T + t)*H + h
    int t = (row >> 4) & (T_ - 1);      // row/16 % 2048
    float c0 = cosp[t * DH_ + i];
    float s0 = sinp[t * DH_ + i];
    float c1 = cosp[t * DH_ + i + 32];
    float s1 = sinp[t * DH_ + i + 32];
    size_t base = (size_t)row * DH_;

    float q0 = Q[base + i], q1 = Q[base + i + 32];
    Q[base + i]      = q0 * c0 - q1 * s0;
    Q[base + i + 32] = q1 * c1 + q0 * s1;

    float k0 = Kv[base + i], k1 = Kv[base + i + 32];
    Kv[base + i]      = k0 * c0 - k1 * s0;
    Kv[base + i + 32] = k1 * c1 + k0 * s1;
}

// ---------------------------------------------------------------------------
// Flash attention (fp32, causal). One query row per thread, 128 q rows/block.
// K/V tiles of 16 rows in smem. Online softmax with per-tile rescale.
// Grid: (T/128, H, B). Layout of Q/K/V/O: (B, T, H, Dh) contiguous.
// ---------------------------------------------------------------------------
__global__ __launch_bounds__(128) void attn_kernel(const float* __restrict__ Q,
                                                   const float* __restrict__ Kv,
                                                   const float* __restrict__ Vv,
                                                   float* __restrict__ O)
{
    const float SCALE = 0.125f;   // 1/sqrt(64)
    int b = blockIdx.z, h = blockIdx.y;
    int qrow = blockIdx.x * 128 + threadIdx.x;

    const size_t bh_off = ((size_t)b * T_ * H_ + h) * DH_;
    const float* qp = Q + bh_off + (size_t)qrow * H_ * DH_;

    float q[64];
    #pragma unroll
    for (int d = 0; d < 64; d += 4) {
        float4 v = *(const float4*)(qp + d);
        q[d] = v.x; q[d + 1] = v.y; q[d + 2] = v.z; q[d + 3] = v.w;
    }

    float acc[64];
    #pragma unroll
    for (int d = 0; d < 64; d++) acc[d] = 0.f;
    float m = -1e30f, l = 0.f;

    __shared__ float Ks[16][64];
    __shared__ float Vs[16][64];

    int kend = blockIdx.x * 128 + 128;   // exclusive key bound for this block

    for (int j0 = 0; j0 < kend; j0 += 16) {
        __syncthreads();
        // load 16 K rows + 16 V rows: 256 float4 each / 128 threads = 2 each
        #pragma unroll
        for (int e = threadIdx.x; e < 256; e += 128) {
            int r = e >> 4;
            int c4 = (e & 15) * 4;
            size_t g = bh_off + (size_t)(j0 + r) * H_ * DH_ + c4;
            *(float4*)&Ks[r][c4] = *(const float4*)(Kv + g);
            *(float4*)&Vs[r][c4] = *(const float4*)(Vv + g);
        }
        __syncthreads();

        float sc[16];
        #pragma unroll
        for (int j = 0; j < 16; j++) {
            float s = 0.f;
            #pragma unroll
            for (int d = 0; d < 64; d++) s += q[d] * Ks[j][d];
            sc[j] = (j0 + j <= qrow) ? s * SCALE : -1e30f;
        }

        float mt = m;
        #pragma unroll
        for (int j = 0; j < 16; j++) mt = fmaxf(mt, sc[j]);
        float corr = __expf(m - mt);
        m = mt;
        l *= corr;
        #pragma unroll
        for (int d = 0; d < 64; d++) acc[d] *= corr;

        #pragma unroll
        for (int j = 0; j < 16; j++) {
            float p = __expf(sc[j] - m);
            l += p;
            #pragma unroll
            for (int d = 0; d < 64; d++) acc[d] += p * Vs[j][d];
        }
    }

    float inv = 1.f / l;
    float* op = O + bh_off + (size_t)qrow * H_ * DH_;
    #pragma unroll
    for (int d = 0; d < 64; d += 4) {
        float4 v = make_float4(acc[d] * inv, acc[d + 1] * inv,
                               acc[d + 2] * inv, acc[d + 3] * inv);
        *(float4*)(op + d) = v;
    }
}

// ---------------------------------------------------------------------------
extern "C" void kernel_launch(void* const* d_in, const int* in_sizes, int n_in,
                              void* d_out, int out_size)
{
    const float* x    = (const float*)d_in[0];
    const float* cosp = (const float*)d_in[1];
    const float* sinp = (const float*)d_in[2];
    const float* Wq   = (const float*)d_in[3];
    const float* Wk   = (const float*)d_in[4];
    const float* Wv   = (const float*)d_in[5];
    const float* Wo   = (const float*)d_in[6];
    float* out = (float*)d_out;

    float *qp, *kp, *vp, *ap;
    cudaGetSymbolAddress((void**)&qp, g_q);
    cudaGetSymbolAddress((void**)&kp, g_k);
    cudaGetSymbolAddress((void**)&vp, g_v);
    cudaGetSymbolAddress((void**)&ap, g_att);

    dim3 gthr(256);
    dim3 ggrid(D_ / 128, ROWS_ / 128);   // (8, 64)

    // QKV projections
    sgemm128<<<ggrid, gthr>>>(x, Wq, qp, ROWS_, D_, D_);
    sgemm128<<<ggrid, gthr>>>(x, Wk, kp, ROWS_, D_, D_);
    sgemm128<<<ggrid, gthr>>>(x, Wv, vp, ROWS_, D_, D_);

    // RoPE on Q and K
    int rope_total = ROWS_ * H_ * 32;
    rope_kernel<<<(rope_total + 255) / 256, 256>>>(qp, kp, cosp, sinp);

    // Attention
    dim3 agrid(T_ / 128, H_, B_);
    attn_kernel<<<agrid, 128>>>(qp, kp, vp, ap);

    // Output projection
    sgemm128<<<ggrid, gthr>>>(ap, Wo, out, ROWS_, D_, D_);
}

// round 4
// speedup vs baseline: 1.4628x; 1.4628x over previous
#include <cuda_runtime.h>
#include <cuda_bf16.h>
#include <math.h>
#include <stdint.h>

// Problem constants
#define B_  4
#define T_  2048
#define D_  1024
#define H_  16
#define DH_ 64
#define ROWS_ (B_*T_)              // 8192
#define ELEMS_ ((size_t)ROWS_*D_)  // 8,388,608

// Scratch (device globals — no allocation)
__device__ float g_q[ELEMS_];
__device__ float g_k[ELEMS_];
__device__ float g_v[ELEMS_];
__device__ float g_att[ELEMS_];

// ---------------------------------------------------------------------------
// TF32 tensor-core GEMM: C[M,N] = A[M,K] @ B[K,N], row-major fp32 in/out.
// Block tile 128x128, BK=32, 256 threads (8 warps), warp tile 32x64.
// mma.sync.aligned.m16n8k8.row.col.f32.tf32.tf32.f32
// Inputs rounded to TF32 with cvt.rna (unbiased) on the smem store.
// Assumes M%128==0, N%128==0, K%32==0.
// ---------------------------------------------------------------------------
__device__ __forceinline__ float to_tf32(float x) {
    asm("cvt.rna.tf32.f32 %0, %1;" : "=f"(x) : "f"(x));
    return x;
}

__device__ __forceinline__ void mma_tf32(float c[4],
                                         uint32_t a0, uint32_t a1, uint32_t a2, uint32_t a3,
                                         uint32_t b0, uint32_t b1)
{
    asm volatile(
        "mma.sync.aligned.m16n8k8.row.col.f32.tf32.tf32.f32 "
        "{%0,%1,%2,%3}, {%4,%5,%6,%7}, {%8,%9}, {%0,%1,%2,%3};"
        : "+f"(c[0]), "+f"(c[1]), "+f"(c[2]), "+f"(c[3])
        : "r"(a0), "r"(a1), "r"(a2), "r"(a3), "r"(b0), "r"(b1));
}

#define APAD 36   // 128 rows x 36 floats: A-frag banks = (4g+t) -> conflict-free
#define BPAD 136  // 32 rows x 136 floats: B-frag banks = (8t+g) -> conflict-free

__global__ __launch_bounds__(256) void gemm_tf32(const float* __restrict__ A,
                                                 const float* __restrict__ Bm,
                                                 float* __restrict__ C,
                                                 int M, int N, int K)
{
    __shared__ float As[128][APAD];
    __shared__ float Bs[32][BPAD];

    const int tid  = threadIdx.x;
    const int lane = tid & 31;
    const int warp = tid >> 5;
    const int warp_m = warp & 3;    // 4 warps along M (4*32 = 128)
    const int warp_n = warp >> 2;   // 2 warps along N (2*64 = 128)
    const int grp = lane >> 2;      // 0..7
    const int tq  = lane & 3;       // 0..3

    const int row0 = blockIdx.y * 128;
    const int col0 = blockIdx.x * 128;

    // Global-load mappings (4 x float4 per thread for each tile)
    const int a_r = tid >> 3;          // 0..31 (+i*32)
    const int a_c = (tid & 7) * 4;     // 0..28
    const int b_r = tid >> 5;          // 0..7  (+i*8)
    const int b_c = (tid & 31) * 4;    // 0..124

    float acc[2][8][4];
    #pragma unroll
    for (int mi = 0; mi < 2; mi++)
        #pragma unroll
        for (int ni = 0; ni < 8; ni++)
            #pragma unroll
            for (int e = 0; e < 4; e++) acc[mi][ni][e] = 0.f;

    for (int k0 = 0; k0 < K; k0 += 32) {
        // Load A tile 128x32 (cvt to tf32 on store)
        #pragma unroll
        for (int i = 0; i < 4; i++) {
            int r = a_r + i * 32;
            float4 v = *(const float4*)&A[(size_t)(row0 + r) * K + k0 + a_c];
            As[r][a_c + 0] = to_tf32(v.x);
            As[r][a_c + 1] = to_tf32(v.y);
            As[r][a_c + 2] = to_tf32(v.z);
            As[r][a_c + 3] = to_tf32(v.w);
        }
        // Load B tile 32x128
        #pragma unroll
        for (int i = 0; i < 4; i++) {
            int r = b_r + i * 8;
            float4 v = *(const float4*)&Bm[(size_t)(k0 + r) * N + col0 + b_c];
            Bs[r][b_c + 0] = to_tf32(v.x);
            Bs[r][b_c + 1] = to_tf32(v.y);
            Bs[r][b_c + 2] = to_tf32(v.z);
            Bs[r][b_c + 3] = to_tf32(v.w);
        }
        __syncthreads();

        #pragma unroll
        for (int kk = 0; kk < 32; kk += 8) {
            // B fragments: 8 n-blocks x 2 regs
            uint32_t bf[8][2];
            #pragma unroll
            for (int ni = 0; ni < 8; ni++) {
                int cb = warp_n * 64 + ni * 8 + grp;
                bf[ni][0] = __float_as_uint(Bs[kk + tq][cb]);
                bf[ni][1] = __float_as_uint(Bs[kk + tq + 4][cb]);
            }
            #pragma unroll
            for (int mi = 0; mi < 2; mi++) {
                int rb = warp_m * 32 + mi * 16;
                uint32_t a0 = __float_as_uint(As[rb + grp][kk + tq]);
                uint32_t a1 = __float_as_uint(As[rb + grp + 8][kk + tq]);
                uint32_t a2 = __float_as_uint(As[rb + grp][kk + tq + 4]);
                uint32_t a3 = __float_as_uint(As[rb + grp + 8][kk + tq + 4]);
                #pragma unroll
                for (int ni = 0; ni < 8; ni++)
                    mma_tf32(acc[mi][ni], a0, a1, a2, a3, bf[ni][0], bf[ni][1]);
            }
        }
        __syncthreads();
    }

    // Epilogue
    #pragma unroll
    for (int mi = 0; mi < 2; mi++) {
        int r = row0 + warp_m * 32 + mi * 16 + grp;
        #pragma unroll
        for (int ni = 0; ni < 8; ni++) {
            int c = col0 + warp_n * 64 + ni * 8 + tq * 2;
            float2 v0 = make_float2(acc[mi][ni][0], acc[mi][ni][1]);
            float2 v1 = make_float2(acc[mi][ni][2], acc[mi][ni][3]);
            *(float2*)&C[(size_t)r * N + c]       = v0;
            *(float2*)&C[(size_t)(r + 8) * N + c] = v1;
        }
    }
}

// ---------------------------------------------------------------------------
// RoPE: in-place on Q and K. Layout (B*T, H, Dh) contiguous.
// ---------------------------------------------------------------------------
__global__ __launch_bounds__(256) void rope_kernel(float* __restrict__ Q,
                                                   float* __restrict__ Kv,
                                                   const float* __restrict__ cosp,
                                                   const float* __restrict__ sinp)
{
    int idx = blockIdx.x * blockDim.x + threadIdx.x;   // over ROWS_*H_*32
    if (idx >= ROWS_ * H_ * 32) return;
    int i = idx & 31;
    int row = idx >> 5;                 // (b*T + t)*H + h
    int t = (row >> 4) & (T_ - 1);      // row/16 % 2048
    float c0 = cosp[t * DH_ + i];
    float s0 = sinp[t * DH_ + i];
    float c1 = cosp[t * DH_ + i + 32];
    float s1 = sinp[t * DH_ + i + 32];
    size_t base = (size_t)row * DH_;

    float q0 = Q[base + i], q1 = Q[base + i + 32];
    Q[base + i]      = q0 * c0 - q1 * s0;
    Q[base + i + 32] = q1 * c1 + q0 * s1;

    float k0 = Kv[base + i], k1 = Kv[base + i + 32];
    Kv[base + i]      = k0 * c0 - k1 * s0;
    Kv[base + i + 32] = k1 * c1 + k0 * s1;
}

// ---------------------------------------------------------------------------
// Flash attention (fp32, causal). One query row per thread, 128 q rows/block.
// K/V tiles of 16 rows in smem. Online softmax with per-tile rescale.
// Grid: (T/128, H, B). Layout of Q/K/V/O: (B, T, H, Dh) contiguous.
// ---------------------------------------------------------------------------
__global__ __launch_bounds__(128) void attn_kernel(const float* __restrict__ Q,
                                                   const float* __restrict__ Kv,
                                                   const float* __restrict__ Vv,
                                                   float* __restrict__ O)
{
    const float SCALE = 0.125f;   // 1/sqrt(64)
    int b = blockIdx.z, h = blockIdx.y;
    int qrow = blockIdx.x * 128 + threadIdx.x;

    const size_t bh_off = ((size_t)b * T_ * H_ + h) * DH_;
    const float* qp = Q + bh_off + (size_t)qrow * H_ * DH_;

    float q[64];
    #pragma unroll
    for (int d = 0; d < 64; d += 4) {
        float4 v = *(const float4*)(qp + d);
        q[d] = v.x; q[d + 1] = v.y; q[d + 2] = v.z; q[d + 3] = v.w;
    }

    float acc[64];
    #pragma unroll
    for (int d = 0; d < 64; d++) acc[d] = 0.f;
    float m = -1e30f, l = 0.f;

    __shared__ float Ks[16][64];
    __shared__ float Vs[16][64];

    int kend = blockIdx.x * 128 + 128;   // exclusive key bound for this block

    for (int j0 = 0; j0 < kend; j0 += 16) {
        __syncthreads();
        #pragma unroll
        for (int e = threadIdx.x; e < 256; e += 128) {
            int r = e >> 4;
            int c4 = (e & 15) * 4;
            size_t g = bh_off + (size_t)(j0 + r) * H_ * DH_ + c4;
            *(float4*)&Ks[r][c4] = *(const float4*)(Kv + g);
            *(float4*)&Vs[r][c4] = *(const float4*)(Vv + g);
        }
        __syncthreads();

        float sc[16];
        #pragma unroll
        for (int j = 0; j < 16; j++) {
            float s = 0.f;
            #pragma unroll
            for (int d = 0; d < 64; d++) s += q[d] * Ks[j][d];
            sc[j] = (j0 + j <= qrow) ? s * SCALE : -1e30f;
        }

        float mt = m;
        #pragma unroll
        for (int j = 0; j < 16; j++) mt = fmaxf(mt, sc[j]);
        float corr = __expf(m - mt);
        m = mt;
        l *= corr;
        #pragma unroll
        for (int d = 0; d < 64; d++) acc[d] *= corr;

        #pragma unroll
        for (int j = 0; j < 16; j++) {
            float p = __expf(sc[j] - m);
            l += p;
            #pragma unroll
            for (int d = 0; d < 64; d++) acc[d] += p * Vs[j][d];
        }
    }

    float inv = 1.f / l;
    float* op = O + bh_off + (size_t)qrow * H_ * DH_;
    #pragma unroll
    for (int d = 0; d < 64; d += 4) {
        float4 v = make_float4(acc[d] * inv, acc[d + 1] * inv,
                               acc[d + 2] * inv, acc[d + 3] * inv);
        *(float4*)(op + d) = v;
    }
}

// ---------------------------------------------------------------------------
extern "C" void kernel_launch(void* const* d_in, const int* in_sizes, int n_in,
                              void* d_out, int out_size)
{
    const float* x    = (const float*)d_in[0];
    const float* cosp = (const float*)d_in[1];
    const float* sinp = (const float*)d_in[2];
    const float* Wq   = (const float*)d_in[3];
    const float* Wk   = (const float*)d_in[4];
    const float* Wv   = (const float*)d_in[5];
    const float* Wo   = (const float*)d_in[6];
    float* out = (float*)d_out;

    float *qp, *kp, *vp, *ap;
    cudaGetSymbolAddress((void**)&qp, g_q);
    cudaGetSymbolAddress((void**)&kp, g_k);
    cudaGetSymbolAddress((void**)&vp, g_v);
    cudaGetSymbolAddress((void**)&ap, g_att);

    dim3 gthr(256);
    dim3 ggrid(D_ / 128, ROWS_ / 128);   // (8, 64)

    // QKV projections (TF32 tensor cores)
    gemm_tf32<<<ggrid, gthr>>>(x, Wq, qp, ROWS_, D_, D_);
    gemm_tf32<<<ggrid, gthr>>>(x, Wk, kp, ROWS_, D_, D_);
    gemm_tf32<<<ggrid, gthr>>>(x, Wv, vp, ROWS_, D_, D_);

    // RoPE on Q and K
    int rope_total = ROWS_ * H_ * 32;
    rope_kernel<<<(rope_total + 255) / 256, 256>>>(qp, kp, cosp, sinp);

    // Attention
    dim3 agrid(T_ / 128, H_, B_);
    attn_kernel<<<agrid, 128>>>(qp, kp, vp, ap);

    // Output projection (TF32 tensor cores)
    gemm_tf32<<<ggrid, gthr>>>(ap, Wo, out, ROWS_, D_, D_);
}

// round 6
// speedup vs baseline: 3.1778x; 2.1724x over previous
#include <cuda_runtime.h>
#include <cuda_bf16.h>
#include <math.h>
#include <stdint.h>

// Problem constants
#define B_  4
#define T_  2048
#define D_  1024
#define H_  16
#define DH_ 64
#define ROWS_ (B_*T_)              // 8192
#define ELEMS_ ((size_t)ROWS_*D_)  // 8,388,608
#define RSTRIDE_ (H_*DH_)          // 1024 floats per token row

// Scratch (device globals — no allocation)
__device__ float g_q[ELEMS_];
__device__ float g_k[ELEMS_];
__device__ float g_v[ELEMS_];
__device__ float g_att[ELEMS_];

// ---------------------------------------------------------------------------
// Common TF32 helpers
// ---------------------------------------------------------------------------
__device__ __forceinline__ float to_tf32(float x) {
    asm("cvt.rna.tf32.f32 %0, %1;" : "=f"(x) : "f"(x));
    return x;
}

__device__ __forceinline__ void mma_tf32(float c[4],
                                         uint32_t a0, uint32_t a1, uint32_t a2, uint32_t a3,
                                         uint32_t b0, uint32_t b1)
{
    asm volatile(
        "mma.sync.aligned.m16n8k8.row.col.f32.tf32.tf32.f32 "
        "{%0,%1,%2,%3}, {%4,%5,%6,%7}, {%8,%9}, {%0,%1,%2,%3};"
        : "+f"(c[0]), "+f"(c[1]), "+f"(c[2]), "+f"(c[3])
        : "r"(a0), "r"(a1), "r"(a2), "r"(a3), "r"(b0), "r"(b1));
}

// ---------------------------------------------------------------------------
// TF32 tensor-core GEMM: C[M,N] = A[M,K] @ B[K,N], row-major fp32 in/out.
// Block tile 128x128, BK=32, 256 threads (8 warps), warp tile 32x64.
// ---------------------------------------------------------------------------
#define APAD 36
#define BPAD 136

__global__ __launch_bounds__(256) void gemm_tf32(const float* __restrict__ A,
                                                 const float* __restrict__ Bm,
                                                 float* __restrict__ C,
                                                 int M, int N, int K)
{
    __shared__ float As[128][APAD];
    __shared__ float Bs[32][BPAD];

    const int tid  = threadIdx.x;
    const int lane = tid & 31;
    const int warp = tid >> 5;
    const int warp_m = warp & 3;
    const int warp_n = warp >> 2;
    const int grp = lane >> 2;
    const int tq  = lane & 3;

    const int row0 = blockIdx.y * 128;
    const int col0 = blockIdx.x * 128;

    const int a_r = tid >> 3;
    const int a_c = (tid & 7) * 4;
    const int b_r = tid >> 5;
    const int b_c = (tid & 31) * 4;

    float acc[2][8][4];
    #pragma unroll
    for (int mi = 0; mi < 2; mi++)
        #pragma unroll
        for (int ni = 0; ni < 8; ni++)
            #pragma unroll
            for (int e = 0; e < 4; e++) acc[mi][ni][e] = 0.f;

    for (int k0 = 0; k0 < K; k0 += 32) {
        #pragma unroll
        for (int i = 0; i < 4; i++) {
            int r = a_r + i * 32;
            float4 v = *(const float4*)&A[(size_t)(row0 + r) * K + k0 + a_c];
            As[r][a_c + 0] = to_tf32(v.x);
            As[r][a_c + 1] = to_tf32(v.y);
            As[r][a_c + 2] = to_tf32(v.z);
            As[r][a_c + 3] = to_tf32(v.w);
        }
        #pragma unroll
        for (int i = 0; i < 4; i++) {
            int r = b_r + i * 8;
            float4 v = *(const float4*)&Bm[(size_t)(k0 + r) * N + col0 + b_c];
            Bs[r][b_c + 0] = to_tf32(v.x);
            Bs[r][b_c + 1] = to_tf32(v.y);
            Bs[r][b_c + 2] = to_tf32(v.z);
            Bs[r][b_c + 3] = to_tf32(v.w);
        }
        __syncthreads();

        #pragma unroll
        for (int kk = 0; kk < 32; kk += 8) {
            uint32_t bf[8][2];
            #pragma unroll
            for (int ni = 0; ni < 8; ni++) {
                int cb = warp_n * 64 + ni * 8 + grp;
                bf[ni][0] = __float_as_uint(Bs[kk + tq][cb]);
                bf[ni][1] = __float_as_uint(Bs[kk + tq + 4][cb]);
            }
            #pragma unroll
            for (int mi = 0; mi < 2; mi++) {
                int rb = warp_m * 32 + mi * 16;
                uint32_t a0 = __float_as_uint(As[rb + grp][kk + tq]);
                uint32_t a1 = __float_as_uint(As[rb + grp + 8][kk + tq]);
                uint32_t a2 = __float_as_uint(As[rb + grp][kk + tq + 4]);
                uint32_t a3 = __float_as_uint(As[rb + grp + 8][kk + tq + 4]);
                #pragma unroll
                for (int ni = 0; ni < 8; ni++)
                    mma_tf32(acc[mi][ni], a0, a1, a2, a3, bf[ni][0], bf[ni][1]);
            }
        }
        __syncthreads();
    }

    #pragma unroll
    for (int mi = 0; mi < 2; mi++) {
        int r = row0 + warp_m * 32 + mi * 16 + grp;
        #pragma unroll
        for (int ni = 0; ni < 8; ni++) {
            int c = col0 + warp_n * 64 + ni * 8 + tq * 2;
            float2 v0 = make_float2(acc[mi][ni][0], acc[mi][ni][1]);
            float2 v1 = make_float2(acc[mi][ni][2], acc[mi][ni][3]);
            *(float2*)&C[(size_t)r * N + c]       = v0;
            *(float2*)&C[(size_t)(r + 8) * N + c] = v1;
        }
    }
}

// ---------------------------------------------------------------------------
// RoPE: in-place on Q and K. Layout (B*T, H, Dh) contiguous.
// ---------------------------------------------------------------------------
__global__ __launch_bounds__(256) void rope_kernel(float* __restrict__ Q,
                                                   float* __restrict__ Kv,
                                                   const float* __restrict__ cosp,
                                                   const float* __restrict__ sinp)
{
    int idx = blockIdx.x * blockDim.x + threadIdx.x;   // over ROWS_*H_*32
    if (idx >= ROWS_ * H_ * 32) return;
    int i = idx & 31;
    int row = idx >> 5;                 // (b*T + t)*H + h
    int t = (row >> 4) & (T_ - 1);
    float c0 = cosp[t * DH_ + i];
    float s0 = sinp[t * DH_ + i];
    float c1 = cosp[t * DH_ + i + 32];
    float s1 = sinp[t * DH_ + i + 32];
    size_t base = (size_t)row * DH_;

    float q0 = Q[base + i], q1 = Q[base + i + 32];
    Q[base + i]      = q0 * c0 - q1 * s0;
    Q[base + i + 32] = q1 * c1 + q0 * s1;

    float k0 = Kv[base + i], k1 = Kv[base + i + 32];
    Kv[base + i]      = k0 * c0 - k1 * s0;
    Kv[base + i + 32] = k1 * c1 + k0 * s1;
}

// ---------------------------------------------------------------------------
// Tensor-core flash attention (TF32 mma, causal, online softmax).
// Block: 128 q-rows, 8 warps (16 q-rows each). Key tiles of 64.
// Grid: (T/128, H, B). Q/K/V/O layout: (B, T, H, Dh) contiguous.
// ---------------------------------------------------------------------------
__global__ __launch_bounds__(256) void attn_mma(const float* __restrict__ Q,
                                                const float* __restrict__ Kv,
                                                const float* __restrict__ Vv,
                                                float* __restrict__ O)
{
    const float SCALE = 0.125f;    // 1/sqrt(64)
    __shared__ float KsT[64][72];  // [dh][key], pad 72 -> conflict-free B-frags
    __shared__ float Vs[64][72];   // [key][dh], pad 72 -> conflict-free B-frags

    int b = blockIdx.z, h = blockIdx.y;
    int q0 = blockIdx.x * 128;
    int tid = threadIdx.x;
    int lane = tid & 31, warp = tid >> 5;
    int grp = lane >> 2, tq = lane & 3;
    size_t bh = ((size_t)b * T_ * H_ + h) * DH_;

    // Q fragments: rows q0+16w+grp(+8), cols 8ks+tq(+4). tf32-rounded once.
    uint32_t qa[8][4];
    {
        const float* qb = Q + bh + (size_t)(q0 + 16 * warp) * RSTRIDE_;
        #pragma unroll
        for (int ks = 0; ks < 8; ks++) {
            qa[ks][0] = __float_as_uint(to_tf32(qb[(size_t)grp * RSTRIDE_ + 8*ks + tq]));
            qa[ks][1] = __float_as_uint(to_tf32(qb[(size_t)(grp+8) * RSTRIDE_ + 8*ks + tq]));
            qa[ks][2] = __float_as_uint(to_tf32(qb[(size_t)grp * RSTRIDE_ + 8*ks + tq + 4]));
            qa[ks][3] = __float_as_uint(to_tf32(qb[(size_t)(grp+8) * RSTRIDE_ + 8*ks + tq + 4]));
        }
    }

    float oacc[8][4];
    #pragma unroll
    for (int nb = 0; nb < 8; nb++)
        #pragma unroll
        for (int e = 0; e < 4; e++) oacc[nb][e] = 0.f;

    float m0 = -1e30f, m1 = -1e30f, l0 = 0.f, l1 = 0.f;
    const int qw  = q0 + 16 * warp;       // min q-row of this warp
    const int r0g = qw + grp;             // global q-row for c0/c1
    const int r1g = qw + grp + 8;         // global q-row for c2/c3
    const int srcA = 4 * grp + (tq >> 1); // shuffle source for P frag conversion
    const bool hi = (tq & 1);

    const int kend = q0 + 128;
    for (int j0 = 0; j0 < kend; j0 += 64) {
        __syncthreads();
        // V tile: coalesced float4 loads, conflict-free float4-ish stores
        {
            int key = tid >> 4;
            int dh  = (tid & 15) * 4;
            #pragma unroll
            for (int it = 0; it < 4; it++, key += 16) {
                float4 v = *(const float4*)(Vv + bh + (size_t)(j0 + key) * RSTRIDE_ + dh);
                Vs[key][dh + 0] = to_tf32(v.x);
                Vs[key][dh + 1] = to_tf32(v.y);
                Vs[key][dh + 2] = to_tf32(v.z);
                Vs[key][dh + 3] = to_tf32(v.w);
            }
        }
        // K tile, transposed store (lanes = consecutive keys -> conflict-free)
        {
            int key = tid & 63;
            int seg = tid >> 6;
            #pragma unroll
            for (int i = 0; i < 4; i++) {
                int dh = seg * 16 + i * 4;
                float4 v = *(const float4*)(Kv + bh + (size_t)(j0 + key) * RSTRIDE_ + dh);
                KsT[dh + 0][key] = to_tf32(v.x);
                KsT[dh + 1][key] = to_tf32(v.y);
                KsT[dh + 2][key] = to_tf32(v.z);
                KsT[dh + 3][key] = to_tf32(v.w);
            }
        }
        __syncthreads();

        if (j0 > qw + 15) continue;        // warp-uniform: no valid keys for this warp
        const bool full = (j0 + 63 <= qw); // entire tile below diagonal -> no masking

        // Scores: S = Q @ K^T  (16 x 64 per warp)
        float p[8][4];
        #pragma unroll
        for (int nb = 0; nb < 8; nb++)
            #pragma unroll
            for (int e = 0; e < 4; e++) p[nb][e] = 0.f;

        #pragma unroll
        for (int ks = 0; ks < 8; ks++) {
            #pragma unroll
            for (int nb = 0; nb < 8; nb++) {
                uint32_t b0 = __float_as_uint(KsT[8*ks + tq][8*nb + grp]);
                uint32_t b1 = __float_as_uint(KsT[8*ks + tq + 4][8*nb + grp]);
                mma_tf32(p[nb], qa[ks][0], qa[ks][1], qa[ks][2], qa[ks][3], b0, b1);
            }
        }

        // Scale + causal mask + row max
        float mx0 = -1e30f, mx1 = -1e30f;
        #pragma unroll
        for (int nb = 0; nb < 8; nb++) {
            int c = j0 + 8*nb + 2*tq;
            p[nb][0] = (full || c     <= r0g) ? p[nb][0] * SCALE : -1e30f;
            p[nb][1] = (full || c + 1 <= r0g) ? p[nb][1] * SCALE : -1e30f;
            p[nb][2] = (full || c     <= r1g) ? p[nb][2] * SCALE : -1e30f;
            p[nb][3] = (full || c + 1 <= r1g) ? p[nb][3] * SCALE : -1e30f;
            mx0 = fmaxf(mx0, fmaxf(p[nb][0], p[nb][1]));
            mx1 = fmaxf(mx1, fmaxf(p[nb][2], p[nb][3]));
        }
        mx0 = fmaxf(mx0, __shfl_xor_sync(0xffffffffu, mx0, 1));
        mx0 = fmaxf(mx0, __shfl_xor_sync(0xffffffffu, mx0, 2));
        mx1 = fmaxf(mx1, __shfl_xor_sync(0xffffffffu, mx1, 1));
        mx1 = fmaxf(mx1, __shfl_xor_sync(0xffffffffu, mx1, 2));

        float mn0 = fmaxf(m0, mx0), mn1 = fmaxf(m1, mx1);
        float cr0 = __expf(m0 - mn0), cr1 = __expf(m1 - mn1);
        m0 = mn0; m1 = mn1;
        l0 *= cr0; l1 *= cr1;
        #pragma unroll
        for (int nb = 0; nb < 8; nb++) {
            oacc[nb][0] *= cr0; oacc[nb][1] *= cr0;
            oacc[nb][2] *= cr1; oacc[nb][3] *= cr1;
        }

        // exp (tf32-rounded; l sums the rounded values for cancellation)
        #pragma unroll
        for (int nb = 0; nb < 8; nb++) {
            float e0 = to_tf32(__expf(p[nb][0] - m0));
            float e1 = to_tf32(__expf(p[nb][1] - m0));
            float e2 = to_tf32(__expf(p[nb][2] - m1));
            float e3 = to_tf32(__expf(p[nb][3] - m1));
            l0 += e0 + e1; l1 += e2 + e3;
            p[nb][0] = e0; p[nb][1] = e1; p[nb][2] = e2; p[nb][3] = e3;
        }

        // PV: convert P C-frags -> A-frags via quad shuffles, then mma with V
        #pragma unroll
        for (int ks = 0; ks < 8; ks++) {
            float v00 = __shfl_sync(0xffffffffu, p[ks][0], srcA);
            float v01 = __shfl_sync(0xffffffffu, p[ks][1], srcA);
            float v10 = __shfl_sync(0xffffffffu, p[ks][2], srcA);
            float v11 = __shfl_sync(0xffffffffu, p[ks][3], srcA);
            float w00 = __shfl_sync(0xffffffffu, p[ks][0], srcA + 2);
            float w01 = __shfl_sync(0xffffffffu, p[ks][1], srcA + 2);
            float w10 = __shfl_sync(0xffffffffu, p[ks][2], srcA + 2);
            float w11 = __shfl_sync(0xffffffffu, p[ks][3], srcA + 2);
            uint32_t a0 = __float_as_uint(hi ? v01 : v00);
            uint32_t a1 = __float_as_uint(hi ? v11 : v10);
            uint32_t a2 = __float_as_uint(hi ? w01 : w00);
            uint32_t a3 = __float_as_uint(hi ? w11 : w10);
            #pragma unroll
            for (int nb = 0; nb < 8; nb++) {
                uint32_t b0 = __float_as_uint(Vs[8*ks + tq][8*nb + grp]);
                uint32_t b1 = __float_as_uint(Vs[8*ks + tq + 4][8*nb + grp]);
                mma_tf32(oacc[nb], a0, a1, a2, a3, b0, b1);
            }
        }
    }

    // Final: quad-reduce l, normalize, write out
    l0 += __shfl_xor_sync(0xffffffffu, l0, 1);
    l0 += __shfl_xor_sync(0xffffffffu, l0, 2);
    l1 += __shfl_xor_sync(0xffffffffu, l1, 1);
    l1 += __shfl_xor_sync(0xffffffffu, l1, 2);
    float inv0 = 1.f / l0, inv1 = 1.f / l1;

    float* ob = O + bh;
    #pragma unroll
    for (int nb = 0; nb < 8; nb++) {
        int c = 8*nb + 2*tq;
        *(float2*)&ob[(size_t)r0g * RSTRIDE_ + c] =
            make_float2(oacc[nb][0] * inv0, oacc[nb][1] * inv0);
        *(float2*)&ob[(size_t)r1g * RSTRIDE_ + c] =
            make_float2(oacc[nb][2] * inv1, oacc[nb][3] * inv1);
    }
}

// ---------------------------------------------------------------------------
extern "C" void kernel_launch(void* const* d_in, const int* in_sizes, int n_in,
                              void* d_out, int out_size)
{
    const float* x    = (const float*)d_in[0];
    const float* cosp = (const float*)d_in[1];
    const float* sinp = (const float*)d_in[2];
    const float* Wq   = (const float*)d_in[3];
    const float* Wk   = (const float*)d_in[4];
    const float* Wv   = (const float*)d_in[5];
    const float* Wo   = (const float*)d_in[6];
    float* out = (float*)d_out;

    float *qp, *kp, *vp, *ap;
    cudaGetSymbolAddress((void**)&qp, g_q);
    cudaGetSymbolAddress((void**)&kp, g_k);
    cudaGetSymbolAddress((void**)&vp, g_v);
    cudaGetSymbolAddress((void**)&ap, g_att);

    dim3 gthr(256);
    dim3 ggrid(D_ / 128, ROWS_ / 128);   // (8, 64)

    // QKV projections (TF32 tensor cores)
    gemm_tf32<<<ggrid, gthr>>>(x, Wq, qp, ROWS_, D_, D_);
    gemm_tf32<<<ggrid, gthr>>>(x, Wk, kp, ROWS_, D_, D_);
    gemm_tf32<<<ggrid, gthr>>>(x, Wv, vp, ROWS_, D_, D_);

    // RoPE on Q and K
    int rope_total = ROWS_ * H_ * 32;
    rope_kernel<<<(rope_total + 255) / 256, 256>>>(qp, kp, cosp, sinp);

    // Attention (TF32 tensor cores)
    dim3 agrid(T_ / 128, H_, B_);
    attn_mma<<<agrid, 256>>>(qp, kp, vp, ap);

    // Output projection (TF32 tensor cores)
    gemm_tf32<<<ggrid, gthr>>>(ap, Wo, out, ROWS_, D_, D_);
}

// round 7
// speedup vs baseline: 3.6628x; 1.1526x over previous
#include <cuda_runtime.h>
#include <cuda_bf16.h>
#include <math.h>
#include <stdint.h>

// Problem constants
#define B_  4
#define T_  2048
#define D_  1024
#define H_  16
#define DH_ 64
#define ROWS_ (B_*T_)              // 8192
#define ELEMS_ ((size_t)ROWS_*D_)  // 8,388,608
#define RSTRIDE_ (H_*DH_)          // 1024 floats per token row

// Scratch (device globals — no allocation)
__device__ float g_q[ELEMS_];
__device__ float g_k[ELEMS_];
__device__ float g_v[ELEMS_];
__device__ float g_att[ELEMS_];
__device__ float g_xr[ELEMS_];            // tf32-rounded x
__device__ float g_wr[4][(size_t)D_*D_];  // tf32-rounded Wq,Wk,Wv,Wo

// ---------------------------------------------------------------------------
// TF32 helpers
// ---------------------------------------------------------------------------
__device__ __forceinline__ float to_tf32(float x) {
    asm("cvt.rna.tf32.f32 %0, %1;" : "=f"(x) : "f"(x));
    return x;
}

__device__ __forceinline__ void mma_tf32(float c[4],
                                         uint32_t a0, uint32_t a1, uint32_t a2, uint32_t a3,
                                         uint32_t b0, uint32_t b1)
{
    asm volatile(
        "mma.sync.aligned.m16n8k8.row.col.f32.tf32.tf32.f32 "
        "{%0,%1,%2,%3}, {%4,%5,%6,%7}, {%8,%9}, {%0,%1,%2,%3};"
        : "+f"(c[0]), "+f"(c[1]), "+f"(c[2]), "+f"(c[3])
        : "r"(a0), "r"(a1), "r"(a2), "r"(a3), "r"(b0), "r"(b1));
}

__device__ __forceinline__ void cp16(void* s, const void* g) {
    uint32_t sa = (uint32_t)__cvta_generic_to_shared(s);
    asm volatile("cp.async.cg.shared.global [%0], [%1], 16;" :: "r"(sa), "l"(g));
}
#define CP_COMMIT() asm volatile("cp.async.commit_group;")
#define CP_WAIT(n)  asm volatile("cp.async.wait_group %0;" :: "n"(n))

// ---------------------------------------------------------------------------
// Elementwise tf32 rounding pass (float4 vectorized)
// ---------------------------------------------------------------------------
__global__ __launch_bounds__(256) void round_tf32_k(const float* __restrict__ src,
                                                    float* __restrict__ dst, int n4)
{
    int i = blockIdx.x * 256 + threadIdx.x;
    if (i >= n4) return;
    float4 v = ((const float4*)src)[i];
    v.x = to_tf32(v.x); v.y = to_tf32(v.y);
    v.z = to_tf32(v.z); v.w = to_tf32(v.w);
    ((float4*)dst)[i] = v;
}

// ---------------------------------------------------------------------------
// TF32 tensor-core GEMM, cp.async double-buffered.
// C[M,N] = A[M,K] @ B[K,N], row-major. A and B MUST be pre-rounded to tf32
// (mainloop feeds raw bits to mma -> truncation is lossless).
// Block tile 128x128, BK=32, 256 threads (8 warps), warp tile 32x64.
// Dynamic smem: 2 stages x (128x36 + 32x136) floats = 71680 B.
// ---------------------------------------------------------------------------
#define APAD 36
#define BPAD 136
#define STAGE_F (128*APAD + 32*BPAD)   // 8960 floats per stage

__global__ __launch_bounds__(256) void gemm_tf32(const float* __restrict__ A,
                                                 const float* __restrict__ Bm,
                                                 float* __restrict__ C,
                                                 int M, int N, int K)
{
    extern __shared__ float smem[];

    const int tid  = threadIdx.x;
    const int lane = tid & 31;
    const int warp = tid >> 5;
    const int warp_m = warp & 3;
    const int warp_n = warp >> 2;
    const int grp = lane >> 2;
    const int tq  = lane & 3;

    const int row0 = blockIdx.y * 128;
    const int col0 = blockIdx.x * 128;

    const int a_r = tid >> 3;          // 0..31 (+i*32)
    const int a_c = (tid & 7) * 4;     // 0..28
    const int b_r = tid >> 5;          // 0..7  (+i*8)
    const int b_c = (tid & 31) * 4;    // 0..124

    float acc[2][8][4];
    #pragma unroll
    for (int mi = 0; mi < 2; mi++)
        #pragma unroll
        for (int ni = 0; ni < 8; ni++)
            #pragma unroll
            for (int e = 0; e < 4; e++) acc[mi][ni][e] = 0.f;

    // stage fill via cp.async
    auto load_stage = [&](int s, int k0) {
        float* As = smem + s * STAGE_F;
        float* Bs = As + 128 * APAD;
        #pragma unroll
        for (int i = 0; i < 4; i++) {
            int r = a_r + i * 32;
            cp16(&As[r * APAD + a_c], &A[(size_t)(row0 + r) * K + k0 + a_c]);
        }
        #pragma unroll
        for (int i = 0; i < 4; i++) {
            int r = b_r + i * 8;
            cp16(&Bs[r * BPAD + b_c], &Bm[(size_t)(k0 + r) * N + col0 + b_c]);
        }
        CP_COMMIT();
    };

    const int NIT = K >> 5;   // K/32
    load_stage(0, 0);

    for (int it = 0; it < NIT; ++it) {
        if (it + 1 < NIT) {
            load_stage((it + 1) & 1, (it + 1) << 5);
            CP_WAIT(1);
        } else {
            CP_WAIT(0);
        }
        __syncthreads();

        const float* As = smem + (it & 1) * STAGE_F;
        const float* Bs = As + 128 * APAD;

        #pragma unroll
        for (int kk = 0; kk < 32; kk += 8) {
            uint32_t bf[8][2];
            #pragma unroll
            for (int ni = 0; ni < 8; ni++) {
                int cb = warp_n * 64 + ni * 8 + grp;
                bf[ni][0] = __float_as_uint(Bs[(kk + tq) * BPAD + cb]);
                bf[ni][1] = __float_as_uint(Bs[(kk + tq + 4) * BPAD + cb]);
            }
            #pragma unroll
            for (int mi = 0; mi < 2; mi++) {
                int rb = warp_m * 32 + mi * 16;
                uint32_t a0 = __float_as_uint(As[(rb + grp) * APAD + kk + tq]);
                uint32_t a1 = __float_as_uint(As[(rb + grp + 8) * APAD + kk + tq]);
                uint32_t a2 = __float_as_uint(As[(rb + grp) * APAD + kk + tq + 4]);
                uint32_t a3 = __float_as_uint(As[(rb + grp + 8) * APAD + kk + tq + 4]);
                #pragma unroll
                for (int ni = 0; ni < 8; ni++)
                    mma_tf32(acc[mi][ni], a0, a1, a2, a3, bf[ni][0], bf[ni][1]);
            }
        }
        __syncthreads();
    }

    #pragma unroll
    for (int mi = 0; mi < 2; mi++) {
        int r = row0 + warp_m * 32 + mi * 16 + grp;
        #pragma unroll
        for (int ni = 0; ni < 8; ni++) {
            int c = col0 + warp_n * 64 + ni * 8 + tq * 2;
            *(float2*)&C[(size_t)r * N + c]       = make_float2(acc[mi][ni][0], acc[mi][ni][1]);
            *(float2*)&C[(size_t)(r + 8) * N + c] = make_float2(acc[mi][ni][2], acc[mi][ni][3]);
        }
    }
}

// ---------------------------------------------------------------------------
// RoPE: in-place on Q and K. Layout (B*T, H, Dh) contiguous.
// ---------------------------------------------------------------------------
__global__ __launch_bounds__(256) void rope_kernel(float* __restrict__ Q,
                                                   float* __restrict__ Kv,
                                                   const float* __restrict__ cosp,
                                                   const float* __restrict__ sinp)
{
    int idx = blockIdx.x * blockDim.x + threadIdx.x;   // over ROWS_*H_*32
    if (idx >= ROWS_ * H_ * 32) return;
    int i = idx & 31;
    int row = idx >> 5;
    int t = (row >> 4) & (T_ - 1);
    float c0 = cosp[t * DH_ + i];
    float s0 = sinp[t * DH_ + i];
    float c1 = cosp[t * DH_ + i + 32];
    float s1 = sinp[t * DH_ + i + 32];
    size_t base = (size_t)row * DH_;

    float q0 = Q[base + i], q1 = Q[base + i + 32];
    Q[base + i]      = q0 * c0 - q1 * s0;
    Q[base + i + 32] = q1 * c1 + q0 * s1;

    float k0 = Kv[base + i], k1 = Kv[base + i + 32];
    Kv[base + i]      = k0 * c0 - k1 * s0;
    Kv[base + i + 32] = k1 * c1 + k0 * s1;
}

// ---------------------------------------------------------------------------
// Tensor-core flash attention (TF32 mma, causal, online softmax).
// Block: 128 q-rows, 8 warps (16 q-rows each). Key tiles of 64.
// Epilogue rounds output to tf32 (feeds the pre-rounded Wo GEMM).
// ---------------------------------------------------------------------------
__global__ __launch_bounds__(256) void attn_mma(const float* __restrict__ Q,
                                                const float* __restrict__ Kv,
                                                const float* __restrict__ Vv,
                                                float* __restrict__ O)
{
    const float SCALE = 0.125f;    // 1/sqrt(64)
    __shared__ float KsT[64][72];
    __shared__ float Vs[64][72];

    int b = blockIdx.z, h = blockIdx.y;
    int q0 = blockIdx.x * 128;
    int tid = threadIdx.x;
    int lane = tid & 31, warp = tid >> 5;
    int grp = lane >> 2, tq = lane & 3;
    size_t bh = ((size_t)b * T_ * H_ + h) * DH_;

    uint32_t qa[8][4];
    {
        const float* qb = Q + bh + (size_t)(q0 + 16 * warp) * RSTRIDE_;
        #pragma unroll
        for (int ks = 0; ks < 8; ks++) {
            qa[ks][0] = __float_as_uint(to_tf32(qb[(size_t)grp * RSTRIDE_ + 8*ks + tq]));
            qa[ks][1] = __float_as_uint(to_tf32(qb[(size_t)(grp+8) * RSTRIDE_ + 8*ks + tq]));
            qa[ks][2] = __float_as_uint(to_tf32(qb[(size_t)grp * RSTRIDE_ + 8*ks + tq + 4]));
            qa[ks][3] = __float_as_uint(to_tf32(qb[(size_t)(grp+8) * RSTRIDE_ + 8*ks + tq + 4]));
        }
    }

    float oacc[8][4];
    #pragma unroll
    for (int nb = 0; nb < 8; nb++)
        #pragma unroll
        for (int e = 0; e < 4; e++) oacc[nb][e] = 0.f;

    float m0 = -1e30f, m1 = -1e30f, l0 = 0.f, l1 = 0.f;
    const int qw  = q0 + 16 * warp;
    const int r0g = qw + grp;
    const int r1g = qw + grp + 8;
    const int srcA = 4 * grp + (tq >> 1);
    const bool hi = (tq & 1);

    const int kend = q0 + 128;
    for (int j0 = 0; j0 < kend; j0 += 64) {
        __syncthreads();
        {
            int key = tid >> 4;
            int dh  = (tid & 15) * 4;
            #pragma unroll
            for (int it = 0; it < 4; it++, key += 16) {
                float4 v = *(const float4*)(Vv + bh + (size_t)(j0 + key) * RSTRIDE_ + dh);
                Vs[key][dh + 0] = to_tf32(v.x);
                Vs[key][dh + 1] = to_tf32(v.y);
                Vs[key][dh + 2] = to_tf32(v.z);
                Vs[key][dh + 3] = to_tf32(v.w);
            }
        }
        {
            int key = tid & 63;
            int seg = tid >> 6;
            #pragma unroll
            for (int i = 0; i < 4; i++) {
                int dh = seg * 16 + i * 4;
                float4 v = *(const float4*)(Kv + bh + (size_t)(j0 + key) * RSTRIDE_ + dh);
                KsT[dh + 0][key] = to_tf32(v.x);
                KsT[dh + 1][key] = to_tf32(v.y);
                KsT[dh + 2][key] = to_tf32(v.z);
                KsT[dh + 3][key] = to_tf32(v.w);
            }
        }
        __syncthreads();

        if (j0 > qw + 15) continue;
        const bool full = (j0 + 63 <= qw);

        float p[8][4];
        #pragma unroll
        for (int nb = 0; nb < 8; nb++)
            #pragma unroll
            for (int e = 0; e < 4; e++) p[nb][e] = 0.f;

        #pragma unroll
        for (int ks = 0; ks < 8; ks++) {
            #pragma unroll
            for (int nb = 0; nb < 8; nb++) {
                uint32_t b0 = __float_as_uint(KsT[8*ks + tq][8*nb + grp]);
                uint32_t b1 = __float_as_uint(KsT[8*ks + tq + 4][8*nb + grp]);
                mma_tf32(p[nb], qa[ks][0], qa[ks][1], qa[ks][2], qa[ks][3], b0, b1);
            }
        }

        float mx0 = -1e30f, mx1 = -1e30f;
        #pragma unroll
        for (int nb = 0; nb < 8; nb++) {
            int c = j0 + 8*nb + 2*tq;
            p[nb][0] = (full || c     <= r0g) ? p[nb][0] * SCALE : -1e30f;
            p[nb][1] = (full || c + 1 <= r0g) ? p[nb][1] * SCALE : -1e30f;
            p[nb][2] = (full || c     <= r1g) ? p[nb][2] * SCALE : -1e30f;
            p[nb][3] = (full || c + 1 <= r1g) ? p[nb][3] * SCALE : -1e30f;
            mx0 = fmaxf(mx0, fmaxf(p[nb][0], p[nb][1]));
            mx1 = fmaxf(mx1, fmaxf(p[nb][2], p[nb][3]));
        }
        mx0 = fmaxf(mx0, __shfl_xor_sync(0xffffffffu, mx0, 1));
        mx0 = fmaxf(mx0, __shfl_xor_sync(0xffffffffu, mx0, 2));
        mx1 = fmaxf(mx1, __shfl_xor_sync(0xffffffffu, mx1, 1));
        mx1 = fmaxf(mx1, __shfl_xor_sync(0xffffffffu, mx1, 2));

        float mn0 = fmaxf(m0, mx0), mn1 = fmaxf(m1, mx1);
        float cr0 = __expf(m0 - mn0), cr1 = __expf(m1 - mn1);
        m0 = mn0; m1 = mn1;
        l0 *= cr0; l1 *= cr1;
        #pragma unroll
        for (int nb = 0; nb < 8; nb++) {
            oacc[nb][0] *= cr0; oacc[nb][1] *= cr0;
            oacc[nb][2] *= cr1; oacc[nb][3] *= cr1;
        }

        #pragma unroll
        for (int nb = 0; nb < 8; nb++) {
            float e0 = to_tf32(__expf(p[nb][0] - m0));
            float e1 = to_tf32(__expf(p[nb][1] - m0));
            float e2 = to_tf32(__expf(p[nb][2] - m1));
            float e3 = to_tf32(__expf(p[nb][3] - m1));
            l0 += e0 + e1; l1 += e2 + e3;
            p[nb][0] = e0; p[nb][1] = e1; p[nb][2] = e2; p[nb][3] = e3;
        }

        #pragma unroll
        for (int ks = 0; ks < 8; ks++) {
            float v00 = __shfl_sync(0xffffffffu, p[ks][0], srcA);
            float v01 = __shfl_sync(0xffffffffu, p[ks][1], srcA);
            float v10 = __shfl_sync(0xffffffffu, p[ks][2], srcA);
            float v11 = __shfl_sync(0xffffffffu, p[ks][3], srcA);
            float w00 = __shfl_sync(0xffffffffu, p[ks][0], srcA + 2);
            float w01 = __shfl_sync(0xffffffffu, p[ks][1], srcA + 2);
            float w10 = __shfl_sync(0xffffffffu, p[ks][2], srcA + 2);
            float w11 = __shfl_sync(0xffffffffu, p[ks][3], srcA + 2);
            uint32_t a0 = __float_as_uint(hi ? v01 : v00);
            uint32_t a1 = __float_as_uint(hi ? v11 : v10);
            uint32_t a2 = __float_as_uint(hi ? w01 : w00);
            uint32_t a3 = __float_as_uint(hi ? w11 : w10);
            #pragma unroll
            for (int nb = 0; nb < 8; nb++) {
                uint32_t b0 = __float_as_uint(Vs[8*ks + tq][8*nb + grp]);
                uint32_t b1 = __float_as_uint(Vs[8*ks + tq + 4][8*nb + grp]);
                mma_tf32(oacc[nb], a0, a1, a2, a3, b0, b1);
            }
        }
    }

    l0 += __shfl_xor_sync(0xffffffffu, l0, 1);
    l0 += __shfl_xor_sync(0xffffffffu, l0, 2);
    l1 += __shfl_xor_sync(0xffffffffu, l1, 1);
    l1 += __shfl_xor_sync(0xffffffffu, l1, 2);
    float inv0 = 1.f / l0, inv1 = 1.f / l1;

    // store rounded to tf32 (A operand of the pre-rounded Wo GEMM)
    float* ob = O + bh;
    #pragma unroll
    for (int nb = 0; nb < 8; nb++) {
        int c = 8*nb + 2*tq;
        *(float2*)&ob[(size_t)r0g * RSTRIDE_ + c] =
            make_float2(to_tf32(oacc[nb][0] * inv0), to_tf32(oacc[nb][1] * inv0));
        *(float2*)&ob[(size_t)r1g * RSTRIDE_ + c] =
            make_float2(to_tf32(oacc[nb][2] * inv1), to_tf32(oacc[nb][3] * inv1));
    }
}

// ---------------------------------------------------------------------------
extern "C" void kernel_launch(void* const* d_in, const int* in_sizes, int n_in,
                              void* d_out, int out_size)
{
    const float* x    = (const float*)d_in[0];
    const float* cosp = (const float*)d_in[1];
    const float* sinp = (const float*)d_in[2];
    const float* Wq   = (const float*)d_in[3];
    const float* Wk   = (const float*)d_in[4];
    const float* Wv   = (const float*)d_in[5];
    const float* Wo   = (const float*)d_in[6];
    float* out = (float*)d_out;

    float *qp, *kp, *vp, *ap, *xr, *wr;
    cudaGetSymbolAddress((void**)&qp, g_q);
    cudaGetSymbolAddress((void**)&kp, g_k);
    cudaGetSymbolAddress((void**)&vp, g_v);
    cudaGetSymbolAddress((void**)&ap, g_att);
    cudaGetSymbolAddress((void**)&xr, g_xr);
    cudaGetSymbolAddress((void**)&wr, g_wr);
    float* wqr = wr;
    float* wkr = wr + (size_t)D_ * D_;
    float* wvr = wr + 2 * (size_t)D_ * D_;
    float* wor = wr + 3 * (size_t)D_ * D_;

    const int SMEM_GEMM = 2 * STAGE_F * 4;   // 71680 B
    cudaFuncSetAttribute(gemm_tf32, cudaFuncAttributeMaxDynamicSharedMemorySize, SMEM_GEMM);

    // Pre-round inputs to tf32 (makes GEMM-mainloop truncation lossless)
    int n4x = (int)(ELEMS_ / 4);
    int n4w = D_ * D_ / 4;
    round_tf32_k<<<(n4x + 255) / 256, 256>>>(x,  xr,  n4x);
    round_tf32_k<<<(n4w + 255) / 256, 256>>>(Wq, wqr, n4w);
    round_tf32_k<<<(n4w + 255) / 256, 256>>>(Wk, wkr, n4w);
    round_tf32_k<<<(n4w + 255) / 256, 256>>>(Wv, wvr, n4w);
    round_tf32_k<<<(n4w + 255) / 256, 256>>>(Wo, wor, n4w);

    dim3 gthr(256);
    dim3 ggrid(D_ / 128, ROWS_ / 128);   // (8, 64)

    // QKV projections
    gemm_tf32<<<ggrid, gthr, SMEM_GEMM>>>(xr, wqr, qp, ROWS_, D_, D_);
    gemm_tf32<<<ggrid, gthr, SMEM_GEMM>>>(xr, wkr, kp, ROWS_, D_, D_);
    gemm_tf32<<<ggrid, gthr, SMEM_GEMM>>>(xr, wvr, vp, ROWS_, D_, D_);

    // RoPE on Q and K
    int rope_total = ROWS_ * H_ * 32;
    rope_kernel<<<(rope_total + 255) / 256, 256>>>(qp, kp, cosp, sinp);

    // Attention (TF32 tensor cores)
    dim3 agrid(T_ / 128, H_, B_);
    attn_mma<<<agrid, 256>>>(qp, kp, vp, ap);

    // Output projection
    gemm_tf32<<<ggrid, gthr, SMEM_GEMM>>>(ap, wor, out, ROWS_, D_, D_);
}

// round 9
// speedup vs baseline: 4.5822x; 1.2510x over previous
#include <cuda_runtime.h>
#include <cuda_bf16.h>
#include <math.h>
#include <stdint.h>

// Problem constants
#define B_  4
#define T_  2048
#define D_  1024
#define H_  16
#define DH_ 64
#define ROWS_ (B_*T_)              // 8192
#define ELEMS_ ((size_t)ROWS_*D_)  // 8,388,608
#define QKVN_ 3072                 // fused QKV width

// Scratch (device globals — no allocation)
__device__ float g_xr[ELEMS_];                       // tf32-rounded x
__device__ float g_wqkv[(size_t)D_*QKVN_];           // packed tf32 [Wq|Wk|Wv], [1024][3072]
__device__ float g_wo[(size_t)D_*D_];                // tf32 Wo [1024][1024]
__device__ float g_qkv[(size_t)ROWS_*QKVN_];         // fused QKV fp32 (tf32-rounded)
__device__ float g_att[ELEMS_];                      // attn out (tf32-rounded)

// ---------------------------------------------------------------------------
// Helpers
// ---------------------------------------------------------------------------
__device__ __forceinline__ float to_tf32(float x) {
    asm("cvt.rna.tf32.f32 %0, %1;" : "=f"(x) : "f"(x));
    return x;
}
__device__ __forceinline__ void mma_tf32(float c[4],
                                         uint32_t a0, uint32_t a1, uint32_t a2, uint32_t a3,
                                         uint32_t b0, uint32_t b1)
{
    asm volatile(
        "mma.sync.aligned.m16n8k8.row.col.f32.tf32.tf32.f32 "
        "{%0,%1,%2,%3}, {%4,%5,%6,%7}, {%8,%9}, {%0,%1,%2,%3};"
        : "+f"(c[0]), "+f"(c[1]), "+f"(c[2]), "+f"(c[3])
        : "r"(a0), "r"(a1), "r"(a2), "r"(a3), "r"(b0), "r"(b1));
}
__device__ __forceinline__ void cp16(void* s, const void* g) {
    uint32_t sa = (uint32_t)__cvta_generic_to_shared(s);
    asm volatile("cp.async.cg.shared.global [%0], [%1], 16;" :: "r"(sa), "l"(g));
}
#define CP_COMMIT() asm volatile("cp.async.commit_group;")
#define CP_WAIT(n)  asm volatile("cp.async.wait_group %0;" :: "n"(n))

// ---------------------------------------------------------------------------
// Prep kernels
// ---------------------------------------------------------------------------
__global__ __launch_bounds__(256) void round_tf32_k(const float* __restrict__ src,
                                                    float* __restrict__ dst, int n4)
{
    int i = blockIdx.x * 256 + threadIdx.x;
    if (i >= n4) return;
    float4 v = ((const float4*)src)[i];
    v.x = to_tf32(v.x); v.y = to_tf32(v.y);
    v.z = to_tf32(v.z); v.w = to_tf32(v.w);
    ((float4*)dst)[i] = v;
}

// Pack W [1024][1024] into out[k][off+n] with tf32 rounding (out stride 3072)
__global__ __launch_bounds__(256) void packw_k(const float* __restrict__ W,
                                               float* __restrict__ out, int off)
{
    int i = blockIdx.x * 256 + threadIdx.x;   // over 1024*1024/4
    if (i >= D_ * D_ / 4) return;
    int k = i >> 8, n4 = i & 255;
    float4 v = ((const float4*)W)[i];
    v.x = to_tf32(v.x); v.y = to_tf32(v.y);
    v.z = to_tf32(v.z); v.w = to_tf32(v.w);
    *(float4*)&out[(size_t)k * QKVN_ + off + n4 * 4] = v;
}

// ---------------------------------------------------------------------------
// TF32 tensor-core GEMM, cp.async double-buffered.
// C[M,N] = A[M,K] @ B[K,N], row-major, inputs pre-rounded to tf32.
// Block tile 128x128, BK=32, 256 threads, warp tile 32x64.
// round_out: round epilogue stores to tf32.
// ---------------------------------------------------------------------------
#define APAD 36
#define BPAD 136
#define STAGE_F (128*APAD + 32*BPAD)   // 8960 floats per stage

__global__ __launch_bounds__(256) void gemm_tf32(const float* __restrict__ A,
                                                 const float* __restrict__ Bm,
                                                 float* __restrict__ C,
                                                 int M, int N, int K, int round_out)
{
    extern __shared__ float smem[];

    const int tid  = threadIdx.x;
    const int lane = tid & 31;
    const int warp = tid >> 5;
    const int warp_m = warp & 3;
    const int warp_n = warp >> 2;
    const int grp = lane >> 2;
    const int tq  = lane & 3;

    const int row0 = blockIdx.y * 128;
    const int col0 = blockIdx.x * 128;

    const int a_r = tid >> 3;
    const int a_c = (tid & 7) * 4;
    const int b_r = tid >> 5;
    const int b_c = (tid & 31) * 4;

    float acc[2][8][4];
    #pragma unroll
    for (int mi = 0; mi < 2; mi++)
        #pragma unroll
        for (int ni = 0; ni < 8; ni++)
            #pragma unroll
            for (int e = 0; e < 4; e++) acc[mi][ni][e] = 0.f;

    auto load_stage = [&](int s, int k0) {
        float* As = smem + s * STAGE_F;
        float* Bs = As + 128 * APAD;
        #pragma unroll
        for (int i = 0; i < 4; i++) {
            int r = a_r + i * 32;
            cp16(&As[r * APAD + a_c], &A[(size_t)(row0 + r) * K + k0 + a_c]);
        }
        #pragma unroll
        for (int i = 0; i < 4; i++) {
            int r = b_r + i * 8;
            cp16(&Bs[r * BPAD + b_c], &Bm[(size_t)(k0 + r) * N + col0 + b_c]);
        }
        CP_COMMIT();
    };

    const int NIT = K >> 5;
    load_stage(0, 0);

    for (int it = 0; it < NIT; ++it) {
        if (it + 1 < NIT) {
            load_stage((it + 1) & 1, (it + 1) << 5);
            CP_WAIT(1);
        } else {
            CP_WAIT(0);
        }
        __syncthreads();

        const float* As = smem + (it & 1) * STAGE_F;
        const float* Bs = As + 128 * APAD;

        #pragma unroll
        for (int kk = 0; kk < 32; kk += 8) {
            uint32_t bf[8][2];
            #pragma unroll
            for (int ni = 0; ni < 8; ni++) {
                int cb = warp_n * 64 + ni * 8 + grp;
                bf[ni][0] = __float_as_uint(Bs[(kk + tq) * BPAD + cb]);
                bf[ni][1] = __float_as_uint(Bs[(kk + tq + 4) * BPAD + cb]);
            }
            #pragma unroll
            for (int mi = 0; mi < 2; mi++) {
                int rb = warp_m * 32 + mi * 16;
                uint32_t a0 = __float_as_uint(As[(rb + grp) * APAD + kk + tq]);
                uint32_t a1 = __float_as_uint(As[(rb + grp + 8) * APAD + kk + tq]);
                uint32_t a2 = __float_as_uint(As[(rb + grp) * APAD + kk + tq + 4]);
                uint32_t a3 = __float_as_uint(As[(rb + grp + 8) * APAD + kk + tq + 4]);
                #pragma unroll
                for (int ni = 0; ni < 8; ni++)
                    mma_tf32(acc[mi][ni], a0, a1, a2, a3, bf[ni][0], bf[ni][1]);
            }
        }
        __syncthreads();
    }

    #pragma unroll
    for (int mi = 0; mi < 2; mi++) {
        int r = row0 + warp_m * 32 + mi * 16 + grp;
        #pragma unroll
        for (int ni = 0; ni < 8; ni++) {
            int c = col0 + warp_n * 64 + ni * 8 + tq * 2;
            float4* dummy;
            if (round_out) {
                *(float2*)&C[(size_t)r * N + c] =
                    make_float2(to_tf32(acc[mi][ni][0]), to_tf32(acc[mi][ni][1]));
                *(float2*)&C[(size_t)(r + 8) * N + c] =
                    make_float2(to_tf32(acc[mi][ni][2]), to_tf32(acc[mi][ni][3]));
            } else {
                *(float2*)&C[(size_t)r * N + c] =
                    make_float2(acc[mi][ni][0], acc[mi][ni][1]);
                *(float2*)&C[(size_t)(r + 8) * N + c] =
                    make_float2(acc[mi][ni][2], acc[mi][ni][3]);
            }
            (void)dummy;
        }
    }
}

// ---------------------------------------------------------------------------
// RoPE: in-place on fused QKV [M][3072]; outputs rounded to tf32.
// ---------------------------------------------------------------------------
__global__ __launch_bounds__(256) void rope_kernel(float* __restrict__ QKV,
                                                   const float* __restrict__ cosp,
                                                   const float* __restrict__ sinp)
{
    int idx = blockIdx.x * blockDim.x + threadIdx.x;   // over ROWS_*H_*32
    if (idx >= ROWS_ * H_ * 32) return;
    int i = idx & 31;
    int row = idx >> 5;                 // m*16 + h
    int m = row >> 4, h = row & 15;
    int t = m & (T_ - 1);
    float c0 = cosp[t * DH_ + i];
    float s0 = sinp[t * DH_ + i];
    float c1 = cosp[t * DH_ + i + 32];
    float s1 = sinp[t * DH_ + i + 32];
    size_t qb = (size_t)m * QKVN_ + h * DH_;

    float q0 = QKV[qb + i], q1 = QKV[qb + i + 32];
    QKV[qb + i]      = to_tf32(q0 * c0 - q1 * s0);
    QKV[qb + i + 32] = to_tf32(q1 * c1 + q0 * s1);

    size_t kb = qb + 1024;
    float k0 = QKV[kb + i], k1 = QKV[kb + i + 32];
    QKV[kb + i]      = to_tf32(k0 * c0 - k1 * s0);
    QKV[kb + i + 32] = to_tf32(k1 * c1 + k0 * s1);
}

// ---------------------------------------------------------------------------
// Tensor-core flash attention (TF32 mma, causal, online softmax).
// cp.async double-buffered K/V tiles (raw copies — Q/K/V pre-rounded to tf32).
// K stored [key][dh] pad 68 (QK^T B-frag bank = 4*grp+tq, conflict-free).
// V stored [key][dh] pad 72 (PV  B-frag bank = 8*tq+grp, conflict-free).
// Block q-index reversed so heavy causal blocks launch first.
// ---------------------------------------------------------------------------
#define KP 68
#define VP 72
#define ATILE_F (64*KP + 64*VP)          // 8960 floats per stage
#define ASMEM (2 * ATILE_F * 4)          // 71680 B

__global__ __launch_bounds__(256) void attn_mma(const float* __restrict__ QKV,
                                                float* __restrict__ O)
{
    const float SCALE = 0.125f;    // 1/sqrt(64)
    extern __shared__ float asm_[];

    int b = blockIdx.z, h = blockIdx.y;
    int q0 = (gridDim.x - 1 - blockIdx.x) * 128;   // reversed: heavy blocks first
    int tid = threadIdx.x;
    int lane = tid & 31, warp = tid >> 5;
    int grp = lane >> 2, tq = lane & 3;
    size_t bq = (size_t)b * T_ * QKVN_ + h * DH_;   // Q base; K = +1024, V = +2048
    size_t bo = (size_t)b * T_ * D_ + h * DH_;      // O base

    // Q fragments: raw bits (already tf32-rounded by rope)
    uint32_t qa[8][4];
    {
        const float* qb = QKV + bq + (size_t)(q0 + 16 * warp) * QKVN_;
        #pragma unroll
        for (int ks = 0; ks < 8; ks++) {
            qa[ks][0] = __float_as_uint(qb[(size_t)grp * QKVN_ + 8*ks + tq]);
            qa[ks][1] = __float_as_uint(qb[(size_t)(grp+8) * QKVN_ + 8*ks + tq]);
            qa[ks][2] = __float_as_uint(qb[(size_t)grp * QKVN_ + 8*ks + tq + 4]);
            qa[ks][3] = __float_as_uint(qb[(size_t)(grp+8) * QKVN_ + 8*ks + tq + 4]);
        }
    }

    float oacc[8][4];
    #pragma unroll
    for (int nb = 0; nb < 8; nb++)
        #pragma unroll
        for (int e = 0; e < 4; e++) oacc[nb][e] = 0.f;

    float m0 = -1e30f, m1 = -1e30f, l0 = 0.f, l1 = 0.f;
    const int qw  = q0 + 16 * warp;
    const int r0g = qw + grp;
    const int r1g = qw + grp + 8;
    const int srcA = 4 * grp + (tq >> 1);
    const bool hi = (tq & 1);

    // cp.async tile fill: 2048 x 16B segs (K then V), 8 per thread
    auto load_tile = [&](int s, int j0) {
        float* base = asm_ + s * ATILE_F;
        #pragma unroll
        for (int i = 0; i < 8; i++) {
            int idx = tid + i * 256;
            int mat = idx >> 10;             // 0=K, 1=V
            int r   = (idx >> 4) & 63;
            int dh  = (idx & 15) * 4;
            const float* g = QKV + bq + (mat ? 2048 : 1024) + (size_t)(j0 + r) * QKVN_ + dh;
            float* d = mat ? (base + 64*KP + r*VP + dh) : (base + r*KP + dh);
            cp16(d, g);
        }
        CP_COMMIT();
    };

    const int nt = q0 / 64 + 2;   // tiles of 64 keys, covering [0, q0+128)
    load_tile(0, 0);

    for (int t = 0; t < nt; ++t) {
        if (t + 1 < nt) { load_tile((t + 1) & 1, (t + 1) * 64); CP_WAIT(1); }
        else            { CP_WAIT(0); }
        __syncthreads();

        const int j0 = t * 64;
        const float* Ks = asm_ + (t & 1) * ATILE_F;
        const float* Vs = Ks + 64 * KP;

        if (j0 <= qw + 15) {
            const bool full = (j0 + 63 <= qw);

            float p[8][4];
            #pragma unroll
            for (int nb = 0; nb < 8; nb++)
                #pragma unroll
                for (int e = 0; e < 4; e++) p[nb][e] = 0.f;

            #pragma unroll
            for (int ks = 0; ks < 8; ks++) {
                #pragma unroll
                for (int nb = 0; nb < 8; nb++) {
                    uint32_t b0 = __float_as_uint(Ks[(8*nb + grp) * KP + 8*ks + tq]);
                    uint32_t b1 = __float_as_uint(Ks[(8*nb + grp) * KP + 8*ks + tq + 4]);
                    mma_tf32(p[nb], qa[ks][0], qa[ks][1], qa[ks][2], qa[ks][3], b0, b1);
                }
            }

            float mx0 = -1e30f, mx1 = -1e30f;
            #pragma unroll
            for (int nb = 0; nb < 8; nb++) {
                int c = j0 + 8*nb + 2*tq;
                p[nb][0] = (full || c     <= r0g) ? p[nb][0] * SCALE : -1e30f;
                p[nb][1] = (full || c + 1 <= r0g) ? p[nb][1] * SCALE : -1e30f;
                p[nb][2] = (full || c     <= r1g) ? p[nb][2] * SCALE : -1e30f;
                p[nb][3] = (full || c + 1 <= r1g) ? p[nb][3] * SCALE : -1e30f;
                mx0 = fmaxf(mx0, fmaxf(p[nb][0], p[nb][1]));
                mx1 = fmaxf(mx1, fmaxf(p[nb][2], p[nb][3]));
            }
            mx0 = fmaxf(mx0, __shfl_xor_sync(0xffffffffu, mx0, 1));
            mx0 = fmaxf(mx0, __shfl_xor_sync(0xffffffffu, mx0, 2));
            mx1 = fmaxf(mx1, __shfl_xor_sync(0xffffffffu, mx1, 1));
            mx1 = fmaxf(mx1, __shfl_xor_sync(0xffffffffu, mx1, 2));

            float mn0 = fmaxf(m0, mx0), mn1 = fmaxf(m1, mx1);
            float cr0 = __expf(m0 - mn0), cr1 = __expf(m1 - mn1);
            m0 = mn0; m1 = mn1;
            l0 *= cr0; l1 *= cr1;
            #pragma unroll
            for (int nb = 0; nb < 8; nb++) {
                oacc[nb][0] *= cr0; oacc[nb][1] *= cr0;
                oacc[nb][2] *= cr1; oacc[nb][3] *= cr1;
            }

            #pragma unroll
            for (int nb = 0; nb < 8; nb++) {
                float e0 = to_tf32(__expf(p[nb][0] - m0));
                float e1 = to_tf32(__expf(p[nb][1] - m0));
                float e2 = to_tf32(__expf(p[nb][2] - m1));
                float e3 = to_tf32(__expf(p[nb][3] - m1));
                l0 += e0 + e1; l1 += e2 + e3;
                p[nb][0] = e0; p[nb][1] = e1; p[nb][2] = e2; p[nb][3] = e3;
            }

            #pragma unroll
            for (int ks = 0; ks < 8; ks++) {
                float v00 = __shfl_sync(0xffffffffu, p[ks][0], srcA);
                float v01 = __shfl_sync(0xffffffffu, p[ks][1], srcA);
                float v10 = __shfl_sync(0xffffffffu, p[ks][2], srcA);
                float v11 = __shfl_sync(0xffffffffu, p[ks][3], srcA);
                float w00 = __shfl_sync(0xffffffffu, p[ks][0], srcA + 2);
                float w01 = __shfl_sync(0xffffffffu, p[ks][1], srcA + 2);
                float w10 = __shfl_sync(0xffffffffu, p[ks][2], srcA + 2);
                float w11 = __shfl_sync(0xffffffffu, p[ks][3], srcA + 2);
                uint32_t a0 = __float_as_uint(hi ? v01 : v00);
                uint32_t a1 = __float_as_uint(hi ? v11 : v10);
                uint32_t a2 = __float_as_uint(hi ? w01 : w00);
                uint32_t a3 = __float_as_uint(hi ? w11 : w10);
                #pragma unroll
                for (int nb = 0; nb < 8; nb++) {
                    uint32_t b0 = __float_as_uint(Vs[(8*ks + tq) * VP + 8*nb + grp]);
                    uint32_t b1 = __float_as_uint(Vs[(8*ks + tq + 4) * VP + 8*nb + grp]);
                    mma_tf32(oacc[nb], a0, a1, a2, a3, b0, b1);
                }
            }
        }
        __syncthreads();
    }

    l0 += __shfl_xor_sync(0xffffffffu, l0, 1);
    l0 += __shfl_xor_sync(0xffffffffu, l0, 2);
    l1 += __shfl_xor_sync(0xffffffffu, l1, 1);
    l1 += __shfl_xor_sync(0xffffffffu, l1, 2);
    float inv0 = 1.f / l0, inv1 = 1.f / l1;

    // store rounded to tf32 (A operand of the Wo GEMM)
    float* ob = O + bo;
    #pragma unroll
    for (int nb = 0; nb < 8; nb++) {
        int c = 8*nb + 2*tq;
        *(float2*)&ob[(size_t)r0g * D_ + c] =
            make_float2(to_tf32(oacc[nb][0] * inv0), to_tf32(oacc[nb][1] * inv0));
        *(float2*)&ob[(size_t)r1g * D_ + c] =
            make_float2(to_tf32(oacc[nb][2] * inv1), to_tf32(oacc[nb][3] * inv1));
    }
}

// ---------------------------------------------------------------------------
extern "C" void kernel_launch(void* const* d_in, const int* in_sizes, int n_in,
                              void* d_out, int out_size)
{
    const float* x    = (const float*)d_in[0];
    const float* cosp = (const float*)d_in[1];
    const float* sinp = (const float*)d_in[2];
    const float* Wq   = (const float*)d_in[3];
    const float* Wk   = (const float*)d_in[4];
    const float* Wv   = (const float*)d_in[5];
    const float* Wo   = (const float*)d_in[6];
    float* out = (float*)d_out;

    float *xr, *wqkv, *wo, *qkv, *att;
    cudaGetSymbolAddress((void**)&xr,   g_xr);
    cudaGetSymbolAddress((void**)&wqkv, g_wqkv);
    cudaGetSymbolAddress((void**)&wo,   g_wo);
    cudaGetSymbolAddress((void**)&qkv,  g_qkv);
    cudaGetSymbolAddress((void**)&att,  g_att);

    const int SMEM_GEMM = 2 * STAGE_F * 4;   // 71680 B
    cudaFuncSetAttribute(gemm_tf32, cudaFuncAttributeMaxDynamicSharedMemorySize, SMEM_GEMM);
    cudaFuncSetAttribute(attn_mma,  cudaFuncAttributeMaxDynamicSharedMemorySize, ASMEM);

    // Prep: round x; pack+round weights
    int n4x = (int)(ELEMS_ / 4);
    int n4w = D_ * D_ / 4;
    round_tf32_k<<<(n4x + 255) / 256, 256>>>(x,  xr, n4x);
    packw_k<<<(n4w + 255) / 256, 256>>>(Wq, wqkv, 0);
    packw_k<<<(n4w + 255) / 256, 256>>>(Wk, wqkv, 1024);
    packw_k<<<(n4w + 255) / 256, 256>>>(Wv, wqkv, 2048);
    round_tf32_k<<<(n4w + 255) / 256, 256>>>(Wo, wo, n4w);

    // Fused QKV projection (epilogue rounds to tf32)
    dim3 qgrid(QKVN_ / 128, ROWS_ / 128);   // (24, 64)
    gemm_tf32<<<qgrid, 256, SMEM_GEMM>>>(xr, wqkv, qkv, ROWS_, QKVN_, D_, 1);

    // RoPE on Q and K (tf32-rounded stores)
    int rope_total = ROWS_ * H_ * 32;
    rope_kernel<<<(rope_total + 255) / 256, 256>>>(qkv, cosp, sinp);

    // Attention
    dim3 agrid(T_ / 128, H_, B_);
    attn_mma<<<agrid, 256, ASMEM>>>(qkv, att);

    // Output projection (no rounding on final output)
    dim3 ogrid(D_ / 128, ROWS_ / 128);      // (8, 64)
    gemm_tf32<<<ogrid, 256, SMEM_GEMM>>>(att, wo, out, ROWS_, D_, D_, 0);
}

// round 11
// speedup vs baseline: 7.1463x; 1.5596x over previous
#include <cuda_runtime.h>
#include <cuda_fp16.h>
#include <math.h>
#include <stdint.h>

// Problem constants
#define B_  4
#define T_  2048
#define D_  1024
#define H_  16
#define DH_ 64
#define ROWS_ (B_*T_)              // 8192
#define ELEMS_ ((size_t)ROWS_*D_)  // 8,388,608
#define QKVN_ 3072                 // fused QKV width

// Scratch (device globals — no allocation)
__device__ __half g_xh[ELEMS_];                    // fp16 x            [M][1024]
__device__ __half g_wqkvh[(size_t)QKVN_*D_];       // fp16 [Wq|Wk|Wv]^T [3072][1024]
__device__ __half g_woh[(size_t)D_*D_];            // fp16 Wo^T         [1024][1024]
__device__ float  g_qkv[(size_t)ROWS_*QKVN_];      // fused QKV fp32    [M][3072]
__device__ __half g_qh[ELEMS_];                    // fp16 Q (roped, *1/8) [M][1024]
__device__ __half g_kh[ELEMS_];                    // fp16 K (roped)       [M][1024]
__device__ __half g_vh[ELEMS_];                    // fp16 V^T   [B*H][64 dh][2048 t]
__device__ __half g_ah[ELEMS_];                    // fp16 attn out     [M][1024]

// ---------------------------------------------------------------------------
// Helpers
// ---------------------------------------------------------------------------
__device__ __forceinline__ void mma_f16(float c[4],
                                        uint32_t a0, uint32_t a1, uint32_t a2, uint32_t a3,
                                        uint32_t b0, uint32_t b1)
{
    asm volatile(
        "mma.sync.aligned.m16n8k16.row.col.f32.f16.f16.f32 "
        "{%0,%1,%2,%3}, {%4,%5,%6,%7}, {%8,%9}, {%0,%1,%2,%3};"
        : "+f"(c[0]), "+f"(c[1]), "+f"(c[2]), "+f"(c[3])
        : "r"(a0), "r"(a1), "r"(a2), "r"(a3), "r"(b0), "r"(b1));
}
__device__ __forceinline__ void cp16(void* s, const void* g) {
    uint32_t sa = (uint32_t)__cvta_generic_to_shared(s);
    asm volatile("cp.async.cg.shared.global [%0], [%1], 16;" :: "r"(sa), "l"(g));
}
#define CP_COMMIT() asm volatile("cp.async.commit_group;")
#define CP_WAIT(n)  asm volatile("cp.async.wait_group %0;" :: "n"(n))
__device__ __forceinline__ uint32_t ld32(const __half* p) {
    return *reinterpret_cast<const uint32_t*>(p);
}

// ---------------------------------------------------------------------------
// Prep kernels
// ---------------------------------------------------------------------------
__global__ __launch_bounds__(256) void cvt_h(const float* __restrict__ src,
                                             __half* __restrict__ dst, int n4)
{
    int i = blockIdx.x * 256 + threadIdx.x;
    if (i >= n4) return;
    float4 v = ((const float4*)src)[i];
    __half2 h0 = __floats2half2_rn(v.x, v.y);
    __half2 h1 = __floats2half2_rn(v.z, v.w);
    *(uint2*)&dst[(size_t)i * 4] = make_uint2(*(uint32_t*)&h0, *(uint32_t*)&h1);
}

// W [k][n] fp32 -> out[(off+n)][k] fp16 (transpose + convert)
__global__ void packwT_h(const float* __restrict__ W, __half* __restrict__ out, int off)
{
    __shared__ float t[32][33];
    int n0 = blockIdx.x * 32, k0 = blockIdx.y * 32;
    int tx = threadIdx.x, ty = threadIdx.y;   // 32 x 8
    #pragma unroll
    for (int i = 0; i < 4; i++)
        t[ty + 8*i][tx] = W[(size_t)(k0 + ty + 8*i) * D_ + n0 + tx];
    __syncthreads();
    #pragma unroll
    for (int i = 0; i < 4; i++) {
        int n = n0 + ty + 8*i;
        out[(size_t)(off + n) * D_ + k0 + tx] = __float2half_rn(t[tx][ty + 8*i]);
    }
}

// ---------------------------------------------------------------------------
// fp16 tensor-core GEMM: C[M,N] fp32 = A[M,K] @ B^T  (B given as [N][K] fp16).
// Block tile 128x128, BK=64, 256 threads (8 warps), warp tile 32x64.
// cp.async double-buffered. smem row stride 72 fp16 (conflict-free frags).
// ---------------------------------------------------------------------------
#define GSTRIDE 72
#define GSTAGE_H (128*GSTRIDE*2)           // fp16 count per stage (A+B)
#define GSMEM (2 * GSTAGE_H * 2)           // bytes: 73728

__global__ __launch_bounds__(256) void gemm_h(const __half* __restrict__ A,
                                              const __half* __restrict__ Bw,
                                              float* __restrict__ C,
                                              int M, int N, int K)
{
    extern __shared__ __half hsm[];

    const int tid  = threadIdx.x;
    const int lane = tid & 31;
    const int warp = tid >> 5;
    const int warp_m = warp & 3;
    const int warp_n = warp >> 2;
    const int grp = lane >> 2;
    const int tq  = lane & 3;

    const int row0 = blockIdx.y * 128;
    const int col0 = blockIdx.x * 128;

    float acc[2][8][4];
    #pragma unroll
    for (int mi = 0; mi < 2; mi++)
        #pragma unroll
        for (int ni = 0; ni < 8; ni++)
            #pragma unroll
            for (int e = 0; e < 4; e++) acc[mi][ni][e] = 0.f;

    auto load_stage = [&](int s, int k0) {
        __half* As = hsm + s * GSTAGE_H;
        __half* Bs = As + 128 * GSTRIDE;
        const __half* Ag = A + (size_t)row0 * K + k0;
        const __half* Bg = Bw + (size_t)col0 * K + k0;
        #pragma unroll
        for (int i = 0; i < 4; i++) {
            int idx = tid + i * 256;
            int r = idx >> 3, seg = idx & 7;
            cp16(As + r * GSTRIDE + seg * 8, Ag + (size_t)r * K + seg * 8);
            cp16(Bs + r * GSTRIDE + seg * 8, Bg + (size_t)r * K + seg * 8);
        }
        CP_COMMIT();
    };

    const int NIT = K >> 6;   // K/64
    load_stage(0, 0);

    for (int it = 0; it < NIT; ++it) {
        if (it + 1 < NIT) { load_stage((it + 1) & 1, (it + 1) << 6); CP_WAIT(1); }
        else              { CP_WAIT(0); }
        __syncthreads();

        const __half* As = hsm + (it & 1) * GSTAGE_H;
        const __half* Bs = As + 128 * GSTRIDE;

        #pragma unroll
        for (int ks = 0; ks < 4; ks++) {
            const int kk = 16 * ks;
            uint32_t bf[8][2];
            #pragma unroll
            for (int ni = 0; ni < 8; ni++) {
                int cb = warp_n * 64 + ni * 8 + grp;
                bf[ni][0] = ld32(Bs + cb * GSTRIDE + kk + 2*tq);
                bf[ni][1] = ld32(Bs + cb * GSTRIDE + kk + 2*tq + 8);
            }
            #pragma unroll
            for (int mi = 0; mi < 2; mi++) {
                int rb = warp_m * 32 + mi * 16;
                uint32_t a0 = ld32(As + (rb + grp)     * GSTRIDE + kk + 2*tq);
                uint32_t a1 = ld32(As + (rb + grp + 8) * GSTRIDE + kk + 2*tq);
                uint32_t a2 = ld32(As + (rb + grp)     * GSTRIDE + kk + 2*tq + 8);
                uint32_t a3 = ld32(As + (rb + grp + 8) * GSTRIDE + kk + 2*tq + 8);
                #pragma unroll
                for (int ni = 0; ni < 8; ni++)
                    mma_f16(acc[mi][ni], a0, a1, a2, a3, bf[ni][0], bf[ni][1]);
            }
        }
        __syncthreads();
    }

    #pragma unroll
    for (int mi = 0; mi < 2; mi++) {
        int r = row0 + warp_m * 32 + mi * 16 + grp;
        #pragma unroll
        for (int ni = 0; ni < 8; ni++) {
            int c = col0 + warp_n * 64 + ni * 8 + tq * 2;
            *(float2*)&C[(size_t)r * N + c]       = make_float2(acc[mi][ni][0], acc[mi][ni][1]);
            *(float2*)&C[(size_t)(r + 8) * N + c] = make_float2(acc[mi][ni][2], acc[mi][ni][3]);
        }
    }
}

// ---------------------------------------------------------------------------
// RoPE + fp16 convert: reads fused QKV fp32, writes Q (scaled by 1/8) and K fp16.
// ---------------------------------------------------------------------------
__global__ __launch_bounds__(256) void rope_h(const float* __restrict__ QKV,
                                              __half* __restrict__ Qh,
                                              __half* __restrict__ Kh,
                                              const float* __restrict__ cosp,
                                              const float* __restrict__ sinp)
{
    int idx = blockIdx.x * blockDim.x + threadIdx.x;   // over ROWS_*H_*32
    if (idx >= ROWS_ * H_ * 32) return;
    int i = idx & 31;
    int row = idx >> 5;                 // m*16 + h
    int m = row >> 4, h = row & 15;
    int t = m & (T_ - 1);
    float c0 = cosp[t * DH_ + i];
    float s0 = sinp[t * DH_ + i];
    float c1 = cosp[t * DH_ + i + 32];
    float s1 = sinp[t * DH_ + i + 32];
    size_t qb = (size_t)m * QKVN_ + h * DH_;
    size_t ob = (size_t)m * D_ + h * DH_;

    float q0 = QKV[qb + i], q1 = QKV[qb + i + 32];
    Qh[ob + i]      = __float2half_rn((q0 * c0 - q1 * s0) * 0.125f);
    Qh[ob + i + 32] = __float2half_rn((q1 * c1 + q0 * s1) * 0.125f);

    size_t kb = qb + 1024;
    float k0 = QKV[kb + i], k1 = QKV[kb + i + 32];
    Kh[ob + i]      = __float2half_rn(k0 * c0 - k1 * s0);
    Kh[ob + i + 32] = __float2half_rn(k1 * c1 + k0 * s1);
}

// ---------------------------------------------------------------------------
// V transpose + convert: QKV fp32 V-part [t][dh] -> Vh [bh][dh][T] fp16.
// Block (32,8), tile 32 tokens x 32 dh. Grid (T/32, 2, B*H).
// ---------------------------------------------------------------------------
__global__ void vtrans_h(const float* __restrict__ QKV, __half* __restrict__ Vh)
{
    __shared__ float t[32][33];
    int t0 = blockIdx.x * 32, d0 = blockIdx.y * 32;
    int bh = blockIdx.z;                    // b*16 + h
    int b = bh >> 4, h = bh & 15;
    int tx = threadIdx.x, ty = threadIdx.y;
    const float* src = QKV + (size_t)b * T_ * QKVN_ + 2048 + h * DH_;
    #pragma unroll
    for (int i = 0; i < 4; i++)
        t[ty + 8*i][tx] = src[(size_t)(t0 + ty + 8*i) * QKVN_ + d0 + tx];
    __syncthreads();
    __half* dst = Vh + ((size_t)bh * DH_) * T_;
    #pragma unroll
    for (int i = 0; i < 4; i++) {
        int dh = d0 + ty + 8*i;
        dst[(size_t)dh * T_ + t0 + tx] = __float2half_rn(t[tx][ty + 8*i]);
    }
}

// ---------------------------------------------------------------------------
// fp16 tensor-core flash attention (causal, online softmax).
// Block: 128 q-rows, 8 warps (16 q-rows each). Key tiles of 64, double-buffered.
// K tile [key][72] fp16; V tile [dh][72+...] = V^T [dh][key] fp16.
// P C-frag -> A-frag is a pure half2 pack (no shuffles with m16n8k16).
// Scale folded into Q. Block q-order reversed (heavy blocks first).
// ---------------------------------------------------------------------------
#define ASTRIDE 72
#define ATILE_H (64*ASTRIDE*2)     // fp16 per stage (K + V^T)

__global__ __launch_bounds__(256) void attn_h(const __half* __restrict__ Qh,
                                              const __half* __restrict__ Kh,
                                              const __half* __restrict__ Vh,
                                              __half* __restrict__ Oh)
{
    __shared__ __align__(16) __half hsm[2 * ATILE_H];   // 36864 B

    int b = blockIdx.z, h = blockIdx.y;
    int q0 = (gridDim.x - 1 - blockIdx.x) * 128;
    int tid = threadIdx.x;
    int lane = tid & 31, warp = tid >> 5;
    int grp = lane >> 2, tq = lane & 3;

    const __half* Qg = Qh + (size_t)b * T_ * D_ + h * DH_;
    const __half* Kg = Kh + (size_t)b * T_ * D_ + h * DH_;
    const __half* Vg = Vh + ((size_t)(b * H_ + h) * DH_) * T_;
    __half* Og = Oh + (size_t)b * T_ * D_ + h * DH_;

    const int qw  = q0 + 16 * warp;
    const int r0g = qw + grp;
    const int r1g = qw + grp + 8;

    // Q fragments (fp16 pairs, already scaled by 1/8)
    uint32_t qa[4][4];
    #pragma unroll
    for (int ks = 0; ks < 4; ks++) {
        qa[ks][0] = ld32(Qg + (size_t)r0g * D_ + 16*ks + 2*tq);
        qa[ks][1] = ld32(Qg + (size_t)r1g * D_ + 16*ks + 2*tq);
        qa[ks][2] = ld32(Qg + (size_t)r0g * D_ + 16*ks + 2*tq + 8);
        qa[ks][3] = ld32(Qg + (size_t)r1g * D_ + 16*ks + 2*tq + 8);
    }

    float oacc[8][4];
    #pragma unroll
    for (int nb = 0; nb < 8; nb++)
        #pragma unroll
        for (int e = 0; e < 4; e++) oacc[nb][e] = 0.f;

    float m0 = -1e30f, m1 = -1e30f, l0 = 0.f, l1 = 0.f;

    // tile fill: K 512 segs + V 512 segs, 4 per thread
    auto load_tile = [&](int s, int j0) {
        __half* Ks = hsm + s * ATILE_H;
        __half* Vs = Ks + 64 * ASTRIDE;
        #pragma unroll
        for (int i = 0; i < 4; i++) {
            int idx = tid + i * 256;
            int mat = idx >> 9;              // 0=K, 1=V
            int r   = (idx >> 3) & 63;
            int seg = idx & 7;
            if (mat == 0)
                cp16(Ks + r * ASTRIDE + seg * 8, Kg + (size_t)(j0 + r) * D_ + seg * 8);
            else
                cp16(Vs + r * ASTRIDE + seg * 8, Vg + (size_t)r * T_ + j0 + seg * 8);
        }
        CP_COMMIT();
    };

    const int nt = q0 / 64 + 2;
    load_tile(0, 0);

    for (int t = 0; t < nt; ++t) {
        if (t + 1 < nt) { load_tile((t + 1) & 1, (t + 1) * 64); CP_WAIT(1); }
        else            { CP_WAIT(0); }
        __syncthreads();

        const int j0 = t * 64;
        const __half* Ks = hsm + (t & 1) * ATILE_H;
        const __half* Vs = Ks + 64 * ASTRIDE;

        if (j0 <= qw + 15) {
            const bool full = (j0 + 63 <= qw);

            // Scores S = Q @ K^T (pre-scaled)
            float p[8][4];
            #pragma unroll
            for (int nb = 0; nb < 8; nb++)
                #pragma unroll
                for (int e = 0; e < 4; e++) p[nb][e] = 0.f;

            #pragma unroll
            for (int ks = 0; ks < 4; ks++) {
                #pragma unroll
                for (int nb = 0; nb < 8; nb++) {
                    uint32_t b0 = ld32(Ks + (8*nb + grp) * ASTRIDE + 16*ks + 2*tq);
                    uint32_t b1 = ld32(Ks + (8*nb + grp) * ASTRIDE + 16*ks + 2*tq + 8);
                    mma_f16(p[nb], qa[ks][0], qa[ks][1], qa[ks][2], qa[ks][3], b0, b1);
                }
            }

            // causal mask + row max
            float mx0 = -1e30f, mx1 = -1e30f;
            #pragma unroll
            for (int nb = 0; nb < 8; nb++) {
                int c = j0 + 8*nb + 2*tq;
                if (!full) {
                    p[nb][0] = (c     <= r0g) ? p[nb][0] : -1e30f;
                    p[nb][1] = (c + 1 <= r0g) ? p[nb][1] : -1e30f;
                    p[nb][2] = (c     <= r1g) ? p[nb][2] : -1e30f;
                    p[nb][3] = (c + 1 <= r1g) ? p[nb][3] : -1e30f;
                }
                mx0 = fmaxf(mx0, fmaxf(p[nb][0], p[nb][1]));
                mx1 = fmaxf(mx1, fmaxf(p[nb][2], p[nb][3]));
            }
            mx0 = fmaxf(mx0, __shfl_xor_sync(0xffffffffu, mx0, 1));
            mx0 = fmaxf(mx0, __shfl_xor_sync(0xffffffffu, mx0, 2));
            mx1 = fmaxf(mx1, __shfl_xor_sync(0xffffffffu, mx1, 1));
            mx1 = fmaxf(mx1, __shfl_xor_sync(0xffffffffu, mx1, 2));

            float mn0 = fmaxf(m0, mx0), mn1 = fmaxf(m1, mx1);
            float cr0 = __expf(m0 - mn0), cr1 = __expf(m1 - mn1);
            m0 = mn0; m1 = mn1;
            l0 *= cr0; l1 *= cr1;
            #pragma unroll
            for (int nb = 0; nb < 8; nb++) {
                oacc[nb][0] *= cr0; oacc[nb][1] *= cr0;
                oacc[nb][2] *= cr1; oacc[nb][3] *= cr1;
            }

            // exp -> fp16 P packs (l sums the rounded values)
            uint32_t pa01[8], pa23[8];
            #pragma unroll
            for (int nb = 0; nb < 8; nb++) {
                float e0 = __expf(p[nb][0] - m0);
                float e1 = __expf(p[nb][1] - m0);
                float e2 = __expf(p[nb][2] - m1);
                float e3 = __expf(p[nb][3] - m1);
                __half2 h01 = __floats2half2_rn(e0, e1);
                __half2 h23 = __floats2half2_rn(e2, e3);
                float2 f01 = __half22float2(h01);
                float2 f23 = __half22float2(h23);
                l0 += f01.x + f01.y;
                l1 += f23.x + f23.y;
                pa01[nb] = *(uint32_t*)&h01;
                pa23[nb] = *(uint32_t*)&h23;
            }

            // PV: A-frags come directly from packed C-frags (no shuffles)
            #pragma unroll
            for (int ks = 0; ks < 4; ks++) {
                uint32_t a0 = pa01[2*ks];
                uint32_t a1 = pa23[2*ks];
                uint32_t a2 = pa01[2*ks + 1];
                uint32_t a3 = pa23[2*ks + 1];
                #pragma unroll
                for (int nb = 0; nb < 8; nb++) {
                    uint32_t b0 = ld32(Vs + (8*nb + grp) * ASTRIDE + 16*ks + 2*tq);
                    uint32_t b1 = ld32(Vs + (8*nb + grp) * ASTRIDE + 16*ks + 2*tq + 8);
                    mma_f16(oacc[nb], a0, a1, a2, a3, b0, b1);
                }
            }
        }
        __syncthreads();
    }

    l0 += __shfl_xor_sync(0xffffffffu, l0, 1);
    l0 += __shfl_xor_sync(0xffffffffu, l0, 2);
    l1 += __shfl_xor_sync(0xffffffffu, l1, 1);
    l1 += __shfl_xor_sync(0xffffffffu, l1, 2);
    float inv0 = 1.f / l0, inv1 = 1.f / l1;

    // fp16 store (A operand of the Wo GEMM)
    #pragma unroll
    for (int nb = 0; nb < 8; nb++) {
        int c = 8*nb + 2*tq;
        __half2 h0 = __floats2half2_rn(oacc[nb][0] * inv0, oacc[nb][1] * inv0);
        __half2 h1 = __floats2half2_rn(oacc[nb][2] * inv1, oacc[nb][3] * inv1);
        *(uint32_t*)&Og[(size_t)r0g * D_ + c] = *(uint32_t*)&h0;
        *(uint32_t*)&Og[(size_t)r1g * D_ + c] = *(uint32_t*)&h1;
    }
}

// ---------------------------------------------------------------------------
extern "C" void kernel_launch(void* const* d_in, const int* in_sizes, int n_in,
                              void* d_out, int out_size)
{
    const float* x    = (const float*)d_in[0];
    const float* cosp = (const float*)d_in[1];
    const float* sinp = (const float*)d_in[2];
    const float* Wq   = (const float*)d_in[3];
    const float* Wk   = (const float*)d_in[4];
    const float* Wv   = (const float*)d_in[5];
    const float* Wo   = (const float*)d_in[6];
    float* out = (float*)d_out;

    __half *xh, *wqkvh, *woh, *qh, *kh, *vh, *ah;
    float *qkv;
    cudaGetSymbolAddress((void**)&xh,    g_xh);
    cudaGetSymbolAddress((void**)&wqkvh, g_wqkvh);
    cudaGetSymbolAddress((void**)&woh,   g_woh);
    cudaGetSymbolAddress((void**)&qkv,   g_qkv);
    cudaGetSymbolAddress((void**)&qh,    g_qh);
    cudaGetSymbolAddress((void**)&kh,    g_kh);
    cudaGetSymbolAddress((void**)&vh,    g_vh);
    cudaGetSymbolAddress((void**)&ah,    g_ah);

    cudaFuncSetAttribute(gemm_h, cudaFuncAttributeMaxDynamicSharedMemorySize, GSMEM);

    // Prep: convert x; transpose+convert weights
    int n4x = (int)(ELEMS_ / 4);
    cvt_h<<<(n4x + 255) / 256, 256>>>(x, xh, n4x);
    dim3 wthr(32, 8), wgrid(32, 32);
    packwT_h<<<wgrid, wthr>>>(Wq, wqkvh, 0);
    packwT_h<<<wgrid, wthr>>>(Wk, wqkvh, 1024);
    packwT_h<<<wgrid, wthr>>>(Wv, wqkvh, 2048);
    packwT_h<<<wgrid, wthr>>>(Wo, woh, 0);

    // Fused QKV projection (fp16 HMMA, fp32 out)
    dim3 qgrid(QKVN_ / 128, ROWS_ / 128);   // (24, 64)
    gemm_h<<<qgrid, 256, GSMEM>>>(xh, wqkvh, qkv, ROWS_, QKVN_, D_);

    // RoPE + fp16 convert (scale folded into Q); V transpose + convert
    int rope_total = ROWS_ * H_ * 32;
    rope_h<<<(rope_total + 255) / 256, 256>>>(qkv, qh, kh, cosp, sinp);
    dim3 vthr(32, 8), vgrid(T_ / 32, 2, B_ * H_);
    vtrans_h<<<vgrid, vthr>>>(qkv, vh);

    // Attention (fp16 HMMA)
    dim3 agrid(T_ / 128, H_, B_);
    attn_h<<<agrid, 256>>>(qh, kh, vh, ah);

    // Output projection (fp32 out)
    dim3 ogrid(D_ / 128, ROWS_ / 128);      // (8, 64)
    gemm_h<<<ogrid, 256, GSMEM>>>(ah, woh, out, ROWS_, D_, D_);
}